// round 12
// baseline (speedup 1.0000x reference)
#include <cuda_runtime.h>
#include <math.h>

#define BB  8
#define NN1 128
#define NN2 512
#define DD  128
#define MROWS (BB * (NN1 + NN2))   // 5120 combined rows
#define R1   (BB * NN1)            // 1024 graph-1 rows

// ---------------- static device scratch ----------------
__device__ float g_g  [MROWS * DD];
__device__ float g_h  [MROWS * DD];
__device__ float g_hA [MROWS * DD];
__device__ float g_hpart[4 * MROWS * DD];   // split-K partials for hp
__device__ float g_e2 [BB * NN2 * NN2];     // masked symmetric logits (graph2)
__device__ float g_a2 [BB * NN2 * NN2];     // row-softmax R (graph2)
__device__ float g_e1 [BB * NN1 * NN1];
__device__ float g_a1 [BB * NN1 * NN1];
__device__ float g_WA [3 * DD * DD];
__device__ float g_bA [3 * DD];
__device__ float g_P1A[BB * NN1 * DD];
__device__ float g_P1B[BB * NN1 * DD];
__device__ float g_P2A[BB * NN2 * DD];
__device__ float g_P2B[BB * NN2 * DD];
__device__ float g_ZA [BB * NN1 * NN2];
__device__ float g_ZB [BB * NN1 * NN2];
__device__ float g_part[BB * NN1 * 4];

// ---------------- packed f32x2 helpers (Blackwell FFMA2) ----------------
__device__ __forceinline__ unsigned long long pk2(float x, float y) {
    unsigned long long r;
    asm("mov.b64 %0, {%1, %2};" : "=l"(r) : "f"(x), "f"(y));
    return r;
}
__device__ __forceinline__ unsigned long long dup2(float x) {
    unsigned long long r;
    asm("mov.b64 %0, {%1, %1};" : "=l"(r) : "f"(x));
    return r;
}
__device__ __forceinline__ void fma2(unsigned long long& acc, unsigned long long a,
                                     unsigned long long b) {
    asm("fma.rn.f32x2 %0, %1, %2, %0;" : "+l"(acc) : "l"(a), "l"(b));
}
__device__ __forceinline__ float2 unpk(unsigned long long v) {
    float2 r;
    asm("mov.b64 {%0, %1}, %2;" : "=f"(r.x), "=f"(r.y) : "l"(v));
    return r;
}

// ---------------- generic 64x64 NN GEMM body with strides ----------------
__device__ __forceinline__ void gemm64k(const float* __restrict__ A, int lda,
                                        const float* __restrict__ B, int ldb,
                                        const float* __restrict__ bias,
                                        float* __restrict__ C, int ldc,
                                        int K, int m0, int n0) {
    __shared__ float As[16][68];
    __shared__ float Bs[16][68];
    int tid = threadIdx.x;
    int tx = tid & 15, ty = tid >> 4;
    int lm = tid >> 2, lkq = (tid & 3) * 4;
    int lk = tid >> 4, ln = (tid & 15) * 4;
    unsigned long long accp[4][2] = {};
    for (int k0 = 0; k0 < K; k0 += 16) {
        float4 a4 = *(const float4*)&A[(long)(m0 + lm) * lda + k0 + lkq];
        As[lkq + 0][lm] = a4.x; As[lkq + 1][lm] = a4.y;
        As[lkq + 2][lm] = a4.z; As[lkq + 3][lm] = a4.w;
        *(float4*)&Bs[lk][ln] = *(const float4*)&B[(long)(k0 + lk) * ldb + n0 + ln];
        __syncthreads();
        #pragma unroll
        for (int k = 0; k < 16; k++) {
            float4 av = *(float4*)&As[k][ty * 4];
            float4 bv = *(float4*)&Bs[k][tx * 4];
            unsigned long long b01 = pk2(bv.x, bv.y);
            unsigned long long b23 = pk2(bv.z, bv.w);
            float am[4] = {av.x, av.y, av.z, av.w};
            #pragma unroll
            for (int i = 0; i < 4; i++) {
                unsigned long long a2 = dup2(am[i]);
                fma2(accp[i][0], a2, b01);
                fma2(accp[i][1], a2, b23);
            }
        }
        __syncthreads();
    }
    #pragma unroll
    for (int i = 0; i < 4; i++) {
        int m = m0 + ty * 4 + i;
        int n = n0 + tx * 4;
        float2 c01 = unpk(accp[i][0]);
        float2 c23 = unpk(accp[i][1]);
        float4 v;
        v.x = c01.x + (bias ? bias[n + 0] : 0.f);
        v.y = c01.y + (bias ? bias[n + 1] : 0.f);
        v.z = c23.x + (bias ? bias[n + 2] : 0.f);
        v.w = c23.y + (bias ? bias[n + 3] : 0.f);
        *(float4*)&C[(long)m * ldc + n] = v;
    }
}

// ---------------- 64x64 TN GEMM body: C[m,n] = sum_k A[k, m0+m] * B[k, n0+n] ----------------
__device__ __forceinline__ void gemm64tn(const float* __restrict__ A, int lda,
                                         const float* __restrict__ B, int ldb,
                                         float* __restrict__ C, int ldc,
                                         int K, int m0, int n0) {
    __shared__ float As[16][68];
    __shared__ float Bs[16][68];
    int tid = threadIdx.x;
    int tx = tid & 15, ty = tid >> 4;
    int lk = tid >> 4, lq = (tid & 15) * 4;
    unsigned long long accp[4][2] = {};
    for (int k0 = 0; k0 < K; k0 += 16) {
        *(float4*)&As[lk][lq] = *(const float4*)&A[(long)(k0 + lk) * lda + m0 + lq];
        *(float4*)&Bs[lk][lq] = *(const float4*)&B[(long)(k0 + lk) * ldb + n0 + lq];
        __syncthreads();
        #pragma unroll
        for (int k = 0; k < 16; k++) {
            float4 av = *(float4*)&As[k][ty * 4];
            float4 bv = *(float4*)&Bs[k][tx * 4];
            unsigned long long b01 = pk2(bv.x, bv.y);
            unsigned long long b23 = pk2(bv.z, bv.w);
            float am[4] = {av.x, av.y, av.z, av.w};
            #pragma unroll
            for (int i = 0; i < 4; i++) {
                unsigned long long a2 = dup2(am[i]);
                fma2(accp[i][0], a2, b01);
                fma2(accp[i][1], a2, b23);
            }
        }
        __syncthreads();
    }
    #pragma unroll
    for (int i = 0; i < 4; i++) {
        int m = m0 + ty * 4 + i, n = n0 + tx * 4;
        float2 c01 = unpk(accp[i][0]);
        float2 c23 = unpk(accp[i][1]);
        float4 v = {c01.x, c01.y, c23.x, c23.y};
        *(float4*)&C[(long)m * ldc + n] = v;
    }
}

// merged prologue: blocks 0..11 WA[l]=W@A tiles; blocks 12..14 bA[l]=b@A
__global__ void k_pre(const float* __restrict__ W, const float* __restrict__ A,
                      const float* __restrict__ b, float* __restrict__ WA,
                      float* __restrict__ bA) {
    int bx = blockIdx.x;
    if (bx < 12) {
        int l = bx >> 2, t = bx & 3;
        gemm64k(W + (long)l * DD * DD, DD, A + (long)l * DD * DD, DD, nullptr,
                WA + (long)l * DD * DD, DD, DD, (t >> 1) * 64, (t & 1) * 64);
    } else {
        int l = bx - 12, n = threadIdx.x;
        if (n < DD) {
            float acc = 0.f;
            #pragma unroll 8
            for (int k = 0; k < DD; k++)
                acc += b[l * DD + k] * A[((long)l * DD + k) * DD + n];
            bA[l * DD + n] = acc;
        }
    }
}

// embedding for both graphs
__global__ void k_embed_both(const float* __restrict__ X1, const float* __restrict__ X2,
                             const float* __restrict__ W, float* __restrict__ Y) {
    int bn = blockIdx.x;
    const float* src = (bn < R1) ? X1 + (size_t)bn * 54
                                 : X2 + (size_t)(bn - R1) * 54;
    __shared__ float xs[54];
    if (threadIdx.x < 54) xs[threadIdx.x] = src[threadIdx.x];
    __syncthreads();
    int d = threadIdx.x;
    float acc = 0.f;
    #pragma unroll
    for (int l = 0; l < 54; l++) acc += xs[l] * W[l * DD + d];
    Y[(size_t)bn * DD + d] = acc;
}

// h = g@W + b ; hA = g@WA + bA  (one launch, 5120 rows)
__global__ void k_dual(const float* __restrict__ g, const float* __restrict__ W,
                       const float* __restrict__ b, const float* __restrict__ WA,
                       const float* __restrict__ bA, float* __restrict__ h,
                       float* __restrict__ hA) {
    int xi = blockIdx.x;
    const float* B; const float* bias; float* C; int n0;
    if (xi < 2) { B = W;  bias = b;  C = h;  n0 = xi * 64; }
    else        { B = WA; bias = bA; C = hA; n0 = (xi - 2) * 64; }
    gemm64k(g, DD, B, DD, bias, C, DD, DD, blockIdx.y * 64, n0);
}

// masked symmetric logits: L[m,n] = adj>0 ? (hA_m.h_n + h_m.hA_n) : -9e15
// L symmetric -> compute only lower-triangle tiles (x<=y), mirror off-diagonal
// tiles through a smem transpose. Ts row stride = 68 floats (272B = 17*16B),
// so float4 accesses at 4-float-aligned columns stay 16B-aligned.
__global__ void k_ntsym(const float* __restrict__ h, const float* __restrict__ hA,
                        const float* __restrict__ adj2, float* __restrict__ e2,
                        const float* __restrict__ adj1, float* __restrict__ e1) {
    int z = blockIdx.z;
    int N; const float* Hb; const float* Ab; const float* Adj; float* Cb;
    if (z < 8) {
        if (blockIdx.x > blockIdx.y) return;       // triangle only
        N = NN2;
        Hb = h  + ((long)R1 + (long)z * NN2) * DD;
        Ab = hA + ((long)R1 + (long)z * NN2) * DD;
        Adj = adj2 + (long)z * NN2 * NN2;
        Cb = e2 + (long)z * NN2 * NN2;
    } else {
        if (blockIdx.x >= 2 || blockIdx.y >= 2 || blockIdx.x > blockIdx.y) return;
        N = NN1;
        Hb = h  + (long)(z - 8) * NN1 * DD;
        Ab = hA + (long)(z - 8) * NN1 * DD;
        Adj = adj1 + (long)(z - 8) * NN1 * NN1;
        Cb = e1 + (long)(z - 8) * NN1 * NN1;
    }
    __shared__ float AsA[16][68];   // hA rows m (as [k][m])
    __shared__ float AsH[16][68];   // h  rows m
    __shared__ float BsH[16][68];   // h  rows n
    __shared__ float BsA[16][68];   // hA rows n
    __shared__ float Ts[64][68];    // transpose staging for mirrored tile
    int m0 = blockIdx.y * 64, n0 = blockIdx.x * 64;
    bool offdiag = (m0 != n0);
    int tid = threadIdx.x;
    int tx = tid & 15, ty = tid >> 4;
    int lm = tid >> 2, lkq = (tid & 3) * 4;
    unsigned long long accp[4][2] = {};
    for (int k0 = 0; k0 < DD; k0 += 16) {
        float4 aA = *(const float4*)&Ab[(long)(m0 + lm) * DD + k0 + lkq];
        AsA[lkq + 0][lm] = aA.x; AsA[lkq + 1][lm] = aA.y;
        AsA[lkq + 2][lm] = aA.z; AsA[lkq + 3][lm] = aA.w;
        float4 aH = *(const float4*)&Hb[(long)(m0 + lm) * DD + k0 + lkq];
        AsH[lkq + 0][lm] = aH.x; AsH[lkq + 1][lm] = aH.y;
        AsH[lkq + 2][lm] = aH.z; AsH[lkq + 3][lm] = aH.w;
        float4 bH = *(const float4*)&Hb[(long)(n0 + lm) * DD + k0 + lkq];
        BsH[lkq + 0][lm] = bH.x; BsH[lkq + 1][lm] = bH.y;
        BsH[lkq + 2][lm] = bH.z; BsH[lkq + 3][lm] = bH.w;
        float4 bA4 = *(const float4*)&Ab[(long)(n0 + lm) * DD + k0 + lkq];
        BsA[lkq + 0][lm] = bA4.x; BsA[lkq + 1][lm] = bA4.y;
        BsA[lkq + 2][lm] = bA4.z; BsA[lkq + 3][lm] = bA4.w;
        __syncthreads();
        #pragma unroll
        for (int k = 0; k < 16; k++) {
            float4 avA = *(float4*)&AsA[k][ty * 4];
            float4 avH = *(float4*)&AsH[k][ty * 4];
            float4 bvH = *(float4*)&BsH[k][tx * 4];
            float4 bvA = *(float4*)&BsA[k][tx * 4];
            unsigned long long h01 = pk2(bvH.x, bvH.y);
            unsigned long long h23 = pk2(bvH.z, bvH.w);
            unsigned long long A01 = pk2(bvA.x, bvA.y);
            unsigned long long A23 = pk2(bvA.z, bvA.w);
            float amA[4] = {avA.x, avA.y, avA.z, avA.w};
            float amH[4] = {avH.x, avH.y, avH.z, avH.w};
            #pragma unroll
            for (int i = 0; i < 4; i++) {
                unsigned long long dA = dup2(amA[i]);
                unsigned long long dH = dup2(amH[i]);
                fma2(accp[i][0], dA, h01);
                fma2(accp[i][1], dA, h23);
                fma2(accp[i][0], dH, A01);
                fma2(accp[i][1], dH, A23);
            }
        }
        __syncthreads();
    }
    #pragma unroll
    for (int i = 0; i < 4; i++) {
        int m = m0 + ty * 4 + i, n = n0 + tx * 4;
        float2 c01 = unpk(accp[i][0]);
        float2 c23 = unpk(accp[i][1]);
        float4 ad = *(const float4*)&Adj[(long)m * N + n];
        float4 v;
        v.x = (ad.x > 0.f) ? c01.x : -9e15f;
        v.y = (ad.y > 0.f) ? c01.y : -9e15f;
        v.z = (ad.z > 0.f) ? c23.x : -9e15f;
        v.w = (ad.w > 0.f) ? c23.y : -9e15f;
        *(float4*)&Cb[(long)m * N + n] = v;
        if (offdiag) {
            int ml = ty * 4 + i, nl = tx * 4;
            Ts[nl + 0][ml] = v.x;
            Ts[nl + 1][ml] = v.y;
            Ts[nl + 2][ml] = v.z;
            Ts[nl + 3][ml] = v.w;
        }
    }
    if (offdiag) {
        __syncthreads();
        // mirrored tile: Cb[n][m] block at rows n0.., cols m0..
        int r = tid >> 2, cs = (tid & 3) * 16;
        #pragma unroll
        for (int q = 0; q < 4; q++)
            *(float4*)&Cb[(long)(n0 + r) * N + m0 + cs + q * 4] =
                *(float4*)&Ts[r][cs + q * 4];
    }
}

// row softmax of the symmetric masked logits (== column softmax transposed)
__global__ void k_rowsm(const float* __restrict__ e2, float* __restrict__ a2,
                        const float* __restrict__ e1, float* __restrict__ a1) {
    int bx = blockIdx.x;
    int t = threadIdx.x;
    int lane = t & 31, w = t >> 5;
    __shared__ float red[4];
    __shared__ float bcast;
    if (bx < BB * NN2) {
        const float* L = e2 + (long)bx * NN2;
        float* O = a2 + (long)bx * NN2;
        float v[4];
        float m = -3.4e38f;
        #pragma unroll
        for (int q = 0; q < 4; q++) { v[q] = L[t + 128 * q]; m = fmaxf(m, v[q]); }
        #pragma unroll
        for (int o = 16; o > 0; o >>= 1) m = fmaxf(m, __shfl_xor_sync(0xffffffffu, m, o));
        if (lane == 0) red[w] = m;
        __syncthreads();
        if (t == 0) bcast = fmaxf(fmaxf(red[0], red[1]), fmaxf(red[2], red[3]));
        __syncthreads();
        m = bcast;
        float s = 0.f;
        #pragma unroll
        for (int q = 0; q < 4; q++) { v[q] = __expf(v[q] - m); s += v[q]; }
        #pragma unroll
        for (int o = 16; o > 0; o >>= 1) s += __shfl_xor_sync(0xffffffffu, s, o);
        if (lane == 0) red[w] = s;
        __syncthreads();
        if (t == 0) bcast = red[0] + red[1] + red[2] + red[3];
        __syncthreads();
        float inv = 1.f / bcast;
        #pragma unroll
        for (int q = 0; q < 4; q++) O[t + 128 * q] = v[q] * inv;
    } else {
        int row = bx - BB * NN2;
        const float* L = e1 + (long)row * NN1;
        float* O = a1 + (long)row * NN1;
        float v = L[t];
        float m = v;
        #pragma unroll
        for (int o = 16; o > 0; o >>= 1) m = fmaxf(m, __shfl_xor_sync(0xffffffffu, m, o));
        if (lane == 0) red[w] = m;
        __syncthreads();
        if (t == 0) bcast = fmaxf(fmaxf(red[0], red[1]), fmaxf(red[2], red[3]));
        __syncthreads();
        m = bcast;
        float e = __expf(v - m);
        float s = e;
        #pragma unroll
        for (int o = 16; o > 0; o >>= 1) s += __shfl_xor_sync(0xffffffffu, s, o);
        if (lane == 0) red[w] = s;
        __syncthreads();
        if (t == 0) bcast = red[0] + red[1] + red[2] + red[3];
        __syncthreads();
        O[t] = e / bcast;
    }
}

// split-K hp GEMM (TN: hp = R^T @ h)
__global__ void k_hp(const float* __restrict__ a2, const float* __restrict__ a1,
                     const float* __restrict__ h, float* __restrict__ part) {
    int z = blockIdx.z;
    if (z < 8) {
        int chunk = blockIdx.x >> 1, nt = blockIdx.x & 1;
        const float* A = a2 + (long)z * NN2 * NN2 + (long)chunk * 128 * NN2;
        const float* B = h + ((long)R1 + (long)z * NN2 + chunk * 128) * DD;
        float* C = part + (long)chunk * MROWS * DD + ((long)R1 + (long)z * NN2) * DD;
        gemm64tn(A, NN2, B, DD, C, DD, 128, blockIdx.y * 64, nt * 64);
    } else {
        if (blockIdx.x >= 2 || blockIdx.y >= 2) return;
        const float* A = a1 + (long)(z - 8) * NN1 * NN1;
        const float* B = h + (long)(z - 8) * NN1 * DD;
        float* C = part + (long)(z - 8) * NN1 * DD;
        gemm64tn(A, NN1, B, DD, C, DD, NN1, blockIdx.y * 64, blockIdx.x * 64);
    }
}

// gate: hp = relu(sum chunks); c = sigmoid(g.gW1 + hp.gW2 + gb); g = c*g + (1-c)*hp
__global__ void k_gate(float* __restrict__ g, const float* __restrict__ part,
                       const float* __restrict__ gW, const float* __restrict__ gb) {
    long row = blockIdx.x;
    int t = threadIdx.x;
    float hp = part[row * DD + t];
    if (row >= R1) {
        hp += part[(long)1 * MROWS * DD + row * DD + t];
        hp += part[(long)2 * MROWS * DD + row * DD + t];
        hp += part[(long)3 * MROWS * DD + row * DD + t];
    }
    hp = fmaxf(hp, 0.f);
    float x = g[row * DD + t];
    float v = x * gW[t] + hp * gW[DD + t];
    #pragma unroll
    for (int o = 16; o > 0; o >>= 1) v += __shfl_down_sync(0xffffffffu, v, o);
    __shared__ float red[4];
    __shared__ float csh;
    if ((t & 31) == 0) red[t >> 5] = v;
    __syncthreads();
    if (t == 0) {
        float s = red[0] + red[1] + red[2] + red[3] + gb[0];
        csh = 1.f / (1.f + __expf(-s));
    }
    __syncthreads();
    float c = csh;
    g[row * DD + t] = c * x + (1.f - c) * hp;
}

// all 4 pair projections in one launch (z: 0=p1a 1=p1b 2=p2a 3=p2b)
__global__ void k_proj(const float* __restrict__ g,
                       const float* __restrict__ WA1, const float* __restrict__ bA1,
                       const float* __restrict__ WB1, const float* __restrict__ bB1,
                       float* __restrict__ p1a, float* __restrict__ p1b,
                       float* __restrict__ p2a, float* __restrict__ p2b) {
    int z = blockIdx.z;
    const float* A; const float* B; const float* bias; float* C; int mt;
    switch (z) {
        case 0: A = g;            B = WA1;           bias = bA1;   C = p1a; mt = R1 / 64; break;
        case 1: A = g;            B = WB1;           bias = bB1;   C = p1b; mt = R1 / 64; break;
        case 2: A = g + (long)R1 * DD; B = WA1 + DD * DD; bias = nullptr; C = p2a; mt = (BB * NN2) / 64; break;
        default:A = g + (long)R1 * DD; B = WB1 + DD * DD; bias = nullptr; C = p2b; mt = (BB * NN2) / 64; break;
    }
    if ((int)blockIdx.y >= mt) return;
    gemm64k(A, DD, B, DD, bias, C, DD, DD, blockIdx.y * 64, blockIdx.x * 64);
}

// Z[b,i,j] = act( b2 + sum_h relu(P1[i,h]+P2[j,h]) * w2[h] ), 32x32 tiles
__global__ void k_zmat(const float* __restrict__ p1a, const float* __restrict__ p1b,
                       const float* __restrict__ p2a, const float* __restrict__ p2b,
                       const float* __restrict__ w2A, const float* __restrict__ w2B,
                       const float* __restrict__ b2A, const float* __restrict__ b2B,
                       float* __restrict__ ZA, float* __restrict__ ZB) {
    __shared__ float P1s[DD][33];
    __shared__ float P2s[DD][33];
    __shared__ float w2s[DD];
    int z = blockIdx.z;
    int b = z >> 1, mlp = z & 1;
    const float* P1 = (mlp ? p1b : p1a) + (long)b * NN1 * DD;
    const float* P2 = (mlp ? p2b : p2a) + (long)b * NN2 * DD;
    const float* w2 = mlp ? w2B : w2A;
    float b2 = mlp ? b2B[0] : b2A[0];
    float* Z = (mlp ? ZB : ZA) + (long)b * NN1 * NN2;
    int i0 = blockIdx.y * 32, j0 = blockIdx.x * 32;
    int tid = threadIdx.x;
    if (tid < DD) w2s[tid] = w2[tid];
    {
        int row = tid >> 3, cb = (tid & 7) * 16;
        #pragma unroll
        for (int q = 0; q < 4; q++) {
            float4 v1 = *(const float4*)&P1[(long)(i0 + row) * DD + cb + q * 4];
            float4 v2 = *(const float4*)&P2[(long)(j0 + row) * DD + cb + q * 4];
            P1s[cb + q * 4 + 0][row] = v1.x; P1s[cb + q * 4 + 1][row] = v1.y;
            P1s[cb + q * 4 + 2][row] = v1.z; P1s[cb + q * 4 + 3][row] = v1.w;
            P2s[cb + q * 4 + 0][row] = v2.x; P2s[cb + q * 4 + 1][row] = v2.y;
            P2s[cb + q * 4 + 2][row] = v2.z; P2s[cb + q * 4 + 3][row] = v2.w;
        }
    }
    __syncthreads();
    int tx = tid & 15, ty = tid >> 4;
    float a00 = 0.f, a01 = 0.f, a10 = 0.f, a11 = 0.f;
    #pragma unroll 4
    for (int k = 0; k < DD; k++) {
        float w = w2s[k];
        float p0 = P1s[k][ty], p1 = P1s[k][ty + 16];
        float q0 = P2s[k][tx], q1 = P2s[k][tx + 16];
        a00 += fmaxf(p0 + q0, 0.f) * w;
        a01 += fmaxf(p0 + q1, 0.f) * w;
        a10 += fmaxf(p1 + q0, 0.f) * w;
        a11 += fmaxf(p1 + q1, 0.f) * w;
    }
    a00 += b2; a01 += b2; a10 += b2; a11 += b2;
    if (mlp == 0) {
        a00 = 1.f / (1.f + __expf(-a00)); a01 = 1.f / (1.f + __expf(-a01));
        a10 = 1.f / (1.f + __expf(-a10)); a11 = 1.f / (1.f + __expf(-a11));
    } else {
        a00 = tanhf(a00) * 0.2f; a01 = tanhf(a01) * 0.2f;
        a10 = tanhf(a10) * 0.2f; a11 = tanhf(a11) * 0.2f;
    }
    Z[(long)(i0 + ty) * NN2 + j0 + tx]           = a00;
    Z[(long)(i0 + ty) * NN2 + j0 + tx + 16]      = a01;
    Z[(long)(i0 + ty + 16) * NN2 + j0 + tx]      = a10;
    Z[(long)(i0 + ty + 16) * NN2 + j0 + tx + 16] = a11;
}

// elementwise physics + per-(b,i) reduction
__global__ void k_phys(const float* __restrict__ ZA, const float* __restrict__ ZB,
                       const float* __restrict__ pos1, const float* __restrict__ pos2,
                       const float* __restrict__ r1, const float* __restrict__ r2,
                       const float* __restrict__ nm1, const float* __restrict__ nm2,
                       const float* __restrict__ A_int, float* __restrict__ part) {
    int b = blockIdx.x >> 7, i = blockIdx.x & 127;
    int t = threadIdx.x;
    float px = pos1[(b * NN1 + i) * 3 + 0];
    float py = pos1[(b * NN1 + i) * 3 + 1];
    float pz = pos1[(b * NN1 + i) * 3 + 2];
    float rr1 = r1[b * NN1 + i];
    float m1  = nm1[b * NN1 + i];
    size_t zbase = (size_t)b * NN1 * NN2 + (size_t)i * NN2;
    size_t abase = (size_t)b * 8 * NN1 * NN2 + (size_t)i * NN2;
    const size_t chw = (size_t)NN1 * NN2;
    float s0 = 0.f, s1 = 0.f, s2 = 0.f, s3 = 0.f;
    for (int j = t; j < NN2; j += 128) {
        float Aw = ZA[zbase + j];
        float Bw = ZB[zbase + j];
        float dx = px - pos2[(b * NN2 + j) * 3 + 0];
        float dy = py - pos2[(b * NN2 + j) * 3 + 1];
        float dz = pz - pos2[(b * NN2 + j) * 3 + 2];
        float dm = sqrtf(dx * dx + dy * dy + dz * dz + 1e-10f);
        if (dm < 0.5f) dm = 1e10f;
        float dm0 = rr1 + r2[b * NN2 + j] + Bw;
        float dm0s = (dm0 < 1e-4f) ? 1.f : dm0;
        float rq = dm0s / dm;
        float rq2 = rq * rq;
        float r6 = rq2 * rq2 * rq2;
        float evdw = fminf(r6 * r6 - 2.f * r6, 100.f);
        float Aamp = Aw * (0.0356f - 0.0178f) + 0.0178f;
        s0 += Aamp * evdw * m1 * nm2[b * NN2 + j];
        float dmd = dm - dm0;
        float a1 = A_int[abase + 1 * chw + j];
        float a7 = A_int[abase + 7 * chw + j];
        float a6 = A_int[abase + 6 * chw + j];
        s1 += fminf(fmaxf(dmd * a1 * (-1.f / 0.7f), 0.f), 1.f);
        s2 += fminf(fmaxf(dmd * a7 * (-1.f / 0.7f), 0.f), 1.f);
        s3 += fminf(fmaxf((1.5f - dmd) * a6, 0.f), 1.f);
    }
    #pragma unroll
    for (int o = 16; o > 0; o >>= 1) {
        s0 += __shfl_down_sync(0xffffffffu, s0, o);
        s1 += __shfl_down_sync(0xffffffffu, s1, o);
        s2 += __shfl_down_sync(0xffffffffu, s2, o);
        s3 += __shfl_down_sync(0xffffffffu, s3, o);
    }
    __shared__ float acc[4][4];
    int lane = t & 31, w = t >> 5;
    if (lane == 0) { acc[w][0] = s0; acc[w][1] = s1; acc[w][2] = s2; acc[w][3] = s3; }
    __syncthreads();
    if (t < 4)
        part[((size_t)b * NN1 + i) * 4 + t] = acc[0][t] + acc[1][t] + acc[2][t] + acc[3][t];
}

__global__ void k_final(const float* __restrict__ part, const float* __restrict__ rotor,
                        const float* __restrict__ duff, const float* __restrict__ hbc,
                        const float* __restrict__ hyc, const float* __restrict__ vdc,
                        const float* __restrict__ rtc, float* __restrict__ out) {
    int b = blockIdx.x, t = threadIdx.x;
    size_t base = ((size_t)b * NN1 + t) * 4;
    float v0 = part[base + 0], v1 = part[base + 1], v2 = part[base + 2], v3 = part[base + 3];
    #pragma unroll
    for (int o = 16; o > 0; o >>= 1) {
        v0 += __shfl_down_sync(0xffffffffu, v0, o);
        v1 += __shfl_down_sync(0xffffffffu, v1, o);
        v2 += __shfl_down_sync(0xffffffffu, v2, o);
        v3 += __shfl_down_sync(0xffffffffu, v3, o);
    }
    __shared__ float red[4][4];
    if ((t & 31) == 0) {
        int w = t >> 5;
        red[w][0] = v0; red[w][1] = v1; red[w][2] = v2; red[w][3] = v3;
    }
    __syncthreads();
    if (t == 0) {
        float s0 = red[0][0] + red[1][0] + red[2][0] + red[3][0];
        float s1 = red[0][1] + red[1][1] + red[2][1] + red[3][1];
        float s2 = red[0][2] + red[1][2] + red[2][2] + red[3][2];
        float s3 = red[0][3] + red[1][3] + red[2][3] + red[3][3];
        float hb = -hbc[0] * hbc[0];
        float hy = -hyc[0] * hyc[0];
        float inv = 1.f / (1.f + rtc[0] * rtc[0] * rotor[b]);
        out[b * 5 + 0] = s0 * inv;
        out[b * 5 + 1] = s1 * hb * inv;
        out[b * 5 + 2] = s2 * hb * inv;
        out[b * 5 + 3] = s3 * hy * inv;
        out[b * 5 + 4] = duff[b] * vdc[0] * vdc[0] * inv;
    }
}

// ---------------- host side ----------------
extern "C" void kernel_launch(void* const* d_in, const int* in_sizes, int n_in,
                              void* d_out, int out_size) {
    (void)in_sizes; (void)n_in; (void)out_size;
    const float* h1      = (const float*)d_in[0];
    const float* adj1    = (const float*)d_in[1];
    const float* h2      = (const float*)d_in[2];
    const float* adj2    = (const float*)d_in[3];
    const float* A_int   = (const float*)d_in[4];
    const float* pos1    = (const float*)d_in[5];
    const float* pos2    = (const float*)d_in[6];
    const float* rotor   = (const float*)d_in[7];
    const float* vdw_r1  = (const float*)d_in[8];
    const float* vdw_r2  = (const float*)d_in[9];
    const float* duff    = (const float*)d_in[10];
    const float* nm1     = (const float*)d_in[11];
    const float* nm2     = (const float*)d_in[12];
    const float* node_W  = (const float*)d_in[13];
    const float* gat_W   = (const float*)d_in[14];
    const float* gat_b   = (const float*)d_in[15];
    const float* gat_A   = (const float*)d_in[16];
    const float* gate_W  = (const float*)d_in[17];
    const float* gate_b  = (const float*)d_in[18];
    const float* vdwA_W1 = (const float*)d_in[19];
    const float* vdwA_b1 = (const float*)d_in[20];
    const float* vdwA_W2 = (const float*)d_in[21];
    const float* vdwA_b2 = (const float*)d_in[22];
    const float* vdwB_W1 = (const float*)d_in[23];
    const float* vdwB_b1 = (const float*)d_in[24];
    const float* vdwB_W2 = (const float*)d_in[25];
    const float* vdwB_b2 = (const float*)d_in[26];
    const float* hbond   = (const float*)d_in[27];
    const float* hydro   = (const float*)d_in[28];
    const float* vdwc    = (const float*)d_in[29];
    const float* rotc    = (const float*)d_in[30];
    float* out = (float*)d_out;

    float *gp, *hp_, *hAp, *hpart, *e2p, *a2p, *e1p, *a1p, *wap, *bap;
    float *p1a, *p1b, *p2a, *p2b, *zap, *zbp, *partp;
    cudaGetSymbolAddress((void**)&gp,  g_g);
    cudaGetSymbolAddress((void**)&hp_, g_h);
    cudaGetSymbolAddress((void**)&hAp, g_hA);
    cudaGetSymbolAddress((void**)&hpart, g_hpart);
    cudaGetSymbolAddress((void**)&e2p, g_e2);
    cudaGetSymbolAddress((void**)&a2p, g_a2);
    cudaGetSymbolAddress((void**)&e1p, g_e1);
    cudaGetSymbolAddress((void**)&a1p, g_a1);
    cudaGetSymbolAddress((void**)&wap, g_WA);
    cudaGetSymbolAddress((void**)&bap, g_bA);
    cudaGetSymbolAddress((void**)&p1a, g_P1A);
    cudaGetSymbolAddress((void**)&p1b, g_P1B);
    cudaGetSymbolAddress((void**)&p2a, g_P2A);
    cudaGetSymbolAddress((void**)&p2b, g_P2B);
    cudaGetSymbolAddress((void**)&zap, g_ZA);
    cudaGetSymbolAddress((void**)&zbp, g_ZB);
    cudaGetSymbolAddress((void**)&partp, g_part);

    // merged prologue + embedding
    k_pre<<<15, 256>>>(gat_W, gat_A, gat_b, wap, bap);
    k_embed_both<<<MROWS, DD>>>(h1, h2, node_W, gp);

    for (int l = 0; l < 3; l++) {
        const float* W  = gat_W  + (size_t)l * DD * DD;
        const float* bW = gat_b  + (size_t)l * DD;
        const float* WA = wap    + (size_t)l * DD * DD;
        const float* bA = bap    + (size_t)l * DD;
        const float* gW = gate_W + (size_t)l * 2 * DD;
        const float* gb = gate_b + l;
        k_dual<<<dim3(4, MROWS / 64, 1), 256>>>(gp, W, bW, WA, bA, hp_, hAp);
        k_ntsym<<<dim3(8, 8, 16), 256>>>(hp_, hAp, adj2, e2p, adj1, e1p);
        k_rowsm<<<BB * NN2 + BB * NN1, 128>>>(e2p, a2p, e1p, a1p);
        k_hp<<<dim3(8, 8, 16), 256>>>(a2p, a1p, hp_, hpart);
        k_gate<<<MROWS, DD>>>(gp, hpart, gW, gb);
    }

    // pair projections (one launch)
    k_proj<<<dim3(2, 64, 4), 256>>>(gp, vdwA_W1, vdwA_b1, vdwB_W1, vdwB_b1,
                                    p1a, p1b, p2a, p2b);
    // pair bilinear-relu MLP matrices
    k_zmat<<<dim3(16, 4, 16), 256>>>(p1a, p1b, p2a, p2b, vdwA_W2, vdwB_W2,
                                     vdwA_b2, vdwB_b2, zap, zbp);
    // physics + reductions
    k_phys<<<BB * NN1, 128>>>(zap, zbp, pos1, pos2, vdw_r1, vdw_r2, nm1, nm2,
                              A_int, partp);
    k_final<<<BB, 128>>>(partp, rotor, duff, hbond, hydro, vdwc, rotc, out);
}

// round 14
// speedup vs baseline: 1.0390x; 1.0390x over previous
#include <cuda_runtime.h>
#include <math.h>

#define BB  8
#define NN1 128
#define NN2 512
#define DD  128
#define MROWS (BB * (NN1 + NN2))   // 5120 combined rows
#define R1   (BB * NN1)            // 1024 graph-1 rows

// ---------------- static device scratch ----------------
__device__ float g_g  [MROWS * DD];
__device__ float g_h  [MROWS * DD];
__device__ float g_hA [MROWS * DD];
__device__ float g_hpart[4 * MROWS * DD];   // split-K partials for hp
__device__ float g_e2 [BB * NN2 * NN2];     // masked symmetric logits (graph2)
__device__ float g_e1 [BB * NN1 * NN1];
__device__ float2 g_stat[BB * NN2 + BB * NN1];  // per-row (max, 1/sum)
__device__ float g_WA [3 * DD * DD];
__device__ float g_bA [3 * DD];
__device__ float g_P1A[BB * NN1 * DD];
__device__ float g_P1B[BB * NN1 * DD];
__device__ float g_P2A[BB * NN2 * DD];
__device__ float g_P2B[BB * NN2 * DD];
__device__ float g_ZA [BB * NN1 * NN2];
__device__ float g_ZB [BB * NN1 * NN2];
__device__ float g_part[BB * NN1 * 4];

// ---------------- packed f32x2 helpers (Blackwell FFMA2) ----------------
__device__ __forceinline__ unsigned long long pk2(float x, float y) {
    unsigned long long r;
    asm("mov.b64 %0, {%1, %2};" : "=l"(r) : "f"(x), "f"(y));
    return r;
}
__device__ __forceinline__ unsigned long long dup2(float x) {
    unsigned long long r;
    asm("mov.b64 %0, {%1, %1};" : "=l"(r) : "f"(x));
    return r;
}
__device__ __forceinline__ void fma2(unsigned long long& acc, unsigned long long a,
                                     unsigned long long b) {
    asm("fma.rn.f32x2 %0, %1, %2, %0;" : "+l"(acc) : "l"(a), "l"(b));
}
__device__ __forceinline__ float2 unpk(unsigned long long v) {
    float2 r;
    asm("mov.b64 {%0, %1}, %2;" : "=f"(r.x), "=f"(r.y) : "l"(v));
    return r;
}

// ---------------- generic 64x64 NN GEMM body with strides ----------------
__device__ __forceinline__ void gemm64k(const float* __restrict__ A, int lda,
                                        const float* __restrict__ B, int ldb,
                                        const float* __restrict__ bias,
                                        float* __restrict__ C, int ldc,
                                        int K, int m0, int n0) {
    __shared__ float As[16][68];
    __shared__ float Bs[16][68];
    int tid = threadIdx.x;
    int tx = tid & 15, ty = tid >> 4;
    int lm = tid >> 2, lkq = (tid & 3) * 4;
    int lk = tid >> 4, ln = (tid & 15) * 4;
    unsigned long long accp[4][2] = {};
    for (int k0 = 0; k0 < K; k0 += 16) {
        float4 a4 = *(const float4*)&A[(long)(m0 + lm) * lda + k0 + lkq];
        As[lkq + 0][lm] = a4.x; As[lkq + 1][lm] = a4.y;
        As[lkq + 2][lm] = a4.z; As[lkq + 3][lm] = a4.w;
        *(float4*)&Bs[lk][ln] = *(const float4*)&B[(long)(k0 + lk) * ldb + n0 + ln];
        __syncthreads();
        #pragma unroll
        for (int k = 0; k < 16; k++) {
            float4 av = *(float4*)&As[k][ty * 4];
            float4 bv = *(float4*)&Bs[k][tx * 4];
            unsigned long long b01 = pk2(bv.x, bv.y);
            unsigned long long b23 = pk2(bv.z, bv.w);
            float am[4] = {av.x, av.y, av.z, av.w};
            #pragma unroll
            for (int i = 0; i < 4; i++) {
                unsigned long long a2 = dup2(am[i]);
                fma2(accp[i][0], a2, b01);
                fma2(accp[i][1], a2, b23);
            }
        }
        __syncthreads();
    }
    #pragma unroll
    for (int i = 0; i < 4; i++) {
        int m = m0 + ty * 4 + i;
        int n = n0 + tx * 4;
        float2 c01 = unpk(accp[i][0]);
        float2 c23 = unpk(accp[i][1]);
        float4 v;
        v.x = c01.x + (bias ? bias[n + 0] : 0.f);
        v.y = c01.y + (bias ? bias[n + 1] : 0.f);
        v.z = c23.x + (bias ? bias[n + 2] : 0.f);
        v.w = c23.y + (bias ? bias[n + 3] : 0.f);
        *(float4*)&C[(long)m * ldc + n] = v;
    }
}

// merged prologue: blocks 0..11 WA[l]=W@A tiles; blocks 12..14 bA[l]=b@A
__global__ void k_pre(const float* __restrict__ W, const float* __restrict__ A,
                      const float* __restrict__ b, float* __restrict__ WA,
                      float* __restrict__ bA) {
    int bx = blockIdx.x;
    if (bx < 12) {
        int l = bx >> 2, t = bx & 3;
        gemm64k(W + (long)l * DD * DD, DD, A + (long)l * DD * DD, DD, nullptr,
                WA + (long)l * DD * DD, DD, DD, (t >> 1) * 64, (t & 1) * 64);
    } else {
        int l = bx - 12, n = threadIdx.x;
        if (n < DD) {
            float acc = 0.f;
            #pragma unroll 8
            for (int k = 0; k < DD; k++)
                acc += b[l * DD + k] * A[((long)l * DD + k) * DD + n];
            bA[l * DD + n] = acc;
        }
    }
}

// embedding for both graphs
__global__ void k_embed_both(const float* __restrict__ X1, const float* __restrict__ X2,
                             const float* __restrict__ W, float* __restrict__ Y) {
    int bn = blockIdx.x;
    const float* src = (bn < R1) ? X1 + (size_t)bn * 54
                                 : X2 + (size_t)(bn - R1) * 54;
    __shared__ float xs[54];
    if (threadIdx.x < 54) xs[threadIdx.x] = src[threadIdx.x];
    __syncthreads();
    int d = threadIdx.x;
    float acc = 0.f;
    #pragma unroll
    for (int l = 0; l < 54; l++) acc += xs[l] * W[l * DD + d];
    Y[(size_t)bn * DD + d] = acc;
}

// h = g@W + b ; hA = g@WA + bA  (one launch, 5120 rows)
__global__ void k_dual(const float* __restrict__ g, const float* __restrict__ W,
                       const float* __restrict__ b, const float* __restrict__ WA,
                       const float* __restrict__ bA, float* __restrict__ h,
                       float* __restrict__ hA) {
    int xi = blockIdx.x;
    const float* B; const float* bias; float* C; int n0;
    if (xi < 2) { B = W;  bias = b;  C = h;  n0 = xi * 64; }
    else        { B = WA; bias = bA; C = hA; n0 = (xi - 2) * 64; }
    gemm64k(g, DD, B, DD, bias, C, DD, DD, blockIdx.y * 64, n0);
}

// masked symmetric logits: L[m,n] = adj>0 ? (hA_m.h_n + h_m.hA_n) : -9e15
// (R9 full-tile version; L symmetric -> row softmax == column softmax^T)
__global__ void k_ntsym(const float* __restrict__ h, const float* __restrict__ hA,
                        const float* __restrict__ adj2, float* __restrict__ e2,
                        const float* __restrict__ adj1, float* __restrict__ e1) {
    int z = blockIdx.z;
    int N; const float* Hb; const float* Ab; const float* Adj; float* Cb;
    if (z < 8) {
        N = NN2;
        Hb = h  + ((long)R1 + (long)z * NN2) * DD;
        Ab = hA + ((long)R1 + (long)z * NN2) * DD;
        Adj = adj2 + (long)z * NN2 * NN2;
        Cb = e2 + (long)z * NN2 * NN2;
    } else {
        if (blockIdx.x >= 2 || blockIdx.y >= 2) return;
        N = NN1;
        Hb = h  + (long)(z - 8) * NN1 * DD;
        Ab = hA + (long)(z - 8) * NN1 * DD;
        Adj = adj1 + (long)(z - 8) * NN1 * NN1;
        Cb = e1 + (long)(z - 8) * NN1 * NN1;
    }
    __shared__ float AsA[16][68];   // hA rows m (as [k][m])
    __shared__ float AsH[16][68];   // h  rows m
    __shared__ float BsH[16][68];   // h  rows n
    __shared__ float BsA[16][68];   // hA rows n
    int m0 = blockIdx.y * 64, n0 = blockIdx.x * 64;
    int tid = threadIdx.x;
    int tx = tid & 15, ty = tid >> 4;
    int lm = tid >> 2, lkq = (tid & 3) * 4;
    unsigned long long accp[4][2] = {};
    for (int k0 = 0; k0 < DD; k0 += 16) {
        float4 aA = *(const float4*)&Ab[(long)(m0 + lm) * DD + k0 + lkq];
        AsA[lkq + 0][lm] = aA.x; AsA[lkq + 1][lm] = aA.y;
        AsA[lkq + 2][lm] = aA.z; AsA[lkq + 3][lm] = aA.w;
        float4 aH = *(const float4*)&Hb[(long)(m0 + lm) * DD + k0 + lkq];
        AsH[lkq + 0][lm] = aH.x; AsH[lkq + 1][lm] = aH.y;
        AsH[lkq + 2][lm] = aH.z; AsH[lkq + 3][lm] = aH.w;
        float4 bH = *(const float4*)&Hb[(long)(n0 + lm) * DD + k0 + lkq];
        BsH[lkq + 0][lm] = bH.x; BsH[lkq + 1][lm] = bH.y;
        BsH[lkq + 2][lm] = bH.z; BsH[lkq + 3][lm] = bH.w;
        float4 bA4 = *(const float4*)&Ab[(long)(n0 + lm) * DD + k0 + lkq];
        BsA[lkq + 0][lm] = bA4.x; BsA[lkq + 1][lm] = bA4.y;
        BsA[lkq + 2][lm] = bA4.z; BsA[lkq + 3][lm] = bA4.w;
        __syncthreads();
        #pragma unroll
        for (int k = 0; k < 16; k++) {
            float4 avA = *(float4*)&AsA[k][ty * 4];
            float4 avH = *(float4*)&AsH[k][ty * 4];
            float4 bvH = *(float4*)&BsH[k][tx * 4];
            float4 bvA = *(float4*)&BsA[k][tx * 4];
            unsigned long long h01 = pk2(bvH.x, bvH.y);
            unsigned long long h23 = pk2(bvH.z, bvH.w);
            unsigned long long A01 = pk2(bvA.x, bvA.y);
            unsigned long long A23 = pk2(bvA.z, bvA.w);
            float amA[4] = {avA.x, avA.y, avA.z, avA.w};
            float amH[4] = {avH.x, avH.y, avH.z, avH.w};
            #pragma unroll
            for (int i = 0; i < 4; i++) {
                unsigned long long dA = dup2(amA[i]);
                unsigned long long dH = dup2(amH[i]);
                fma2(accp[i][0], dA, h01);
                fma2(accp[i][1], dA, h23);
                fma2(accp[i][0], dH, A01);
                fma2(accp[i][1], dH, A23);
            }
        }
        __syncthreads();
    }
    #pragma unroll
    for (int i = 0; i < 4; i++) {
        int m = m0 + ty * 4 + i, n = n0 + tx * 4;
        float2 c01 = unpk(accp[i][0]);
        float2 c23 = unpk(accp[i][1]);
        float4 ad = *(const float4*)&Adj[(long)m * N + n];
        float4 v;
        v.x = (ad.x > 0.f) ? c01.x : -9e15f;
        v.y = (ad.y > 0.f) ? c01.y : -9e15f;
        v.z = (ad.z > 0.f) ? c23.x : -9e15f;
        v.w = (ad.w > 0.f) ? c23.y : -9e15f;
        *(float4*)&Cb[(long)m * N + n] = v;
    }
}

// per-row softmax stats: stat[row] = (max, 1/sum_exp). rows 0..4095: graph2; then graph1.
__global__ void k_rowstat(const float* __restrict__ e2, const float* __restrict__ e1,
                          float2* __restrict__ stat) {
    int bx = blockIdx.x;
    int t = threadIdx.x;
    int lane = t & 31, w = t >> 5;
    __shared__ float red[4];
    __shared__ float bcast;
    if (bx < BB * NN2) {
        const float* L = e2 + (long)bx * NN2;
        float v[4];
        float m = -3.4e38f;
        #pragma unroll
        for (int q = 0; q < 4; q++) { v[q] = L[t + 128 * q]; m = fmaxf(m, v[q]); }
        #pragma unroll
        for (int o = 16; o > 0; o >>= 1) m = fmaxf(m, __shfl_xor_sync(0xffffffffu, m, o));
        if (lane == 0) red[w] = m;
        __syncthreads();
        if (t == 0) bcast = fmaxf(fmaxf(red[0], red[1]), fmaxf(red[2], red[3]));
        __syncthreads();
        m = bcast;
        float s = 0.f;
        #pragma unroll
        for (int q = 0; q < 4; q++) s += __expf(v[q] - m);
        #pragma unroll
        for (int o = 16; o > 0; o >>= 1) s += __shfl_xor_sync(0xffffffffu, s, o);
        if (lane == 0) red[w] = s;
        __syncthreads();
        if (t == 0) {
            float ss = red[0] + red[1] + red[2] + red[3];
            stat[bx] = make_float2(m, 1.f / ss);
        }
    } else {
        int row = bx - BB * NN2;
        const float* L = e1 + (long)row * NN1;
        float v = L[t];
        float m = v;
        #pragma unroll
        for (int o = 16; o > 0; o >>= 1) m = fmaxf(m, __shfl_xor_sync(0xffffffffu, m, o));
        if (lane == 0) red[w] = m;
        __syncthreads();
        if (t == 0) bcast = fmaxf(fmaxf(red[0], red[1]), fmaxf(red[2], red[3]));
        __syncthreads();
        m = bcast;
        float s = __expf(v - m);
        #pragma unroll
        for (int o = 16; o > 0; o >>= 1) s += __shfl_xor_sync(0xffffffffu, s, o);
        if (lane == 0) red[w] = s;
        __syncthreads();
        if (t == 0) {
            float ss = red[0] + red[1] + red[2] + red[3];
            stat[bx] = make_float2(m, 1.f / ss);
        }
    }
}

// split-K hp GEMM (TN: hp = R^T @ h) with row-softmax applied on load:
// R[k,i] = exp(L[k,i] - m_k) * inv_k
__global__ void k_hp(const float* __restrict__ e2, const float* __restrict__ e1,
                     const float2* __restrict__ stat, const float* __restrict__ h,
                     float* __restrict__ part) {
    int z = blockIdx.z;
    const float* A; int lda, K, statbase;
    const float* B; float* C; int m0, n0;
    if (z < 8) {
        int chunk = blockIdx.x >> 1, nt = blockIdx.x & 1;
        A = e2 + (long)z * NN2 * NN2 + (long)chunk * 128 * NN2;
        lda = NN2; K = 128;
        statbase = z * NN2 + chunk * 128;
        B = h + ((long)R1 + (long)z * NN2 + chunk * 128) * DD;
        C = part + (long)chunk * MROWS * DD + ((long)R1 + (long)z * NN2) * DD;
        m0 = blockIdx.y * 64; n0 = nt * 64;
    } else {
        if (blockIdx.x >= 2 || blockIdx.y >= 2) return;
        A = e1 + (long)(z - 8) * NN1 * NN1;
        lda = NN1; K = NN1;
        statbase = BB * NN2 + (z - 8) * NN1;
        B = h + (long)(z - 8) * NN1 * DD;
        C = part + (long)(z - 8) * NN1 * DD;
        m0 = blockIdx.y * 64; n0 = blockIdx.x * 64;
    }
    __shared__ float As[16][68];
    __shared__ float Bs[16][68];
    int tid = threadIdx.x;
    int tx = tid & 15, ty = tid >> 4;
    int lk = tid >> 4, lq = (tid & 15) * 4;
    unsigned long long accp[4][2] = {};
    for (int k0 = 0; k0 < K; k0 += 16) {
        float2 st = stat[statbase + k0 + lk];
        float4 a4 = *(const float4*)&A[(long)(k0 + lk) * lda + m0 + lq];
        a4.x = __expf(a4.x - st.x) * st.y;
        a4.y = __expf(a4.y - st.x) * st.y;
        a4.z = __expf(a4.z - st.x) * st.y;
        a4.w = __expf(a4.w - st.x) * st.y;
        *(float4*)&As[lk][lq] = a4;
        *(float4*)&Bs[lk][lq] = *(const float4*)&B[(long)(k0 + lk) * DD + n0 + lq];
        __syncthreads();
        #pragma unroll
        for (int k = 0; k < 16; k++) {
            float4 av = *(float4*)&As[k][ty * 4];
            float4 bv = *(float4*)&Bs[k][tx * 4];
            unsigned long long b01 = pk2(bv.x, bv.y);
            unsigned long long b23 = pk2(bv.z, bv.w);
            float am[4] = {av.x, av.y, av.z, av.w};
            #pragma unroll
            for (int i = 0; i < 4; i++) {
                unsigned long long a2 = dup2(am[i]);
                fma2(accp[i][0], a2, b01);
                fma2(accp[i][1], a2, b23);
            }
        }
        __syncthreads();
    }
    #pragma unroll
    for (int i = 0; i < 4; i++) {
        int m = m0 + ty * 4 + i, n = n0 + tx * 4;
        float2 c01 = unpk(accp[i][0]);
        float2 c23 = unpk(accp[i][1]);
        float4 v = {c01.x, c01.y, c23.x, c23.y};
        *(float4*)&C[(long)m * DD + n] = v;
    }
}

// gate: hp = relu(sum chunks); c = sigmoid(g.gW1 + hp.gW2 + gb); g = c*g + (1-c)*hp
__global__ void k_gate(float* __restrict__ g, const float* __restrict__ part,
                       const float* __restrict__ gW, const float* __restrict__ gb) {
    long row = blockIdx.x;
    int t = threadIdx.x;
    float hp = part[row * DD + t];
    if (row >= R1) {
        hp += part[(long)1 * MROWS * DD + row * DD + t];
        hp += part[(long)2 * MROWS * DD + row * DD + t];
        hp += part[(long)3 * MROWS * DD + row * DD + t];
    }
    hp = fmaxf(hp, 0.f);
    float x = g[row * DD + t];
    float v = x * gW[t] + hp * gW[DD + t];
    #pragma unroll
    for (int o = 16; o > 0; o >>= 1) v += __shfl_down_sync(0xffffffffu, v, o);
    __shared__ float red[4];
    __shared__ float csh;
    if ((t & 31) == 0) red[t >> 5] = v;
    __syncthreads();
    if (t == 0) {
        float s = red[0] + red[1] + red[2] + red[3] + gb[0];
        csh = 1.f / (1.f + __expf(-s));
    }
    __syncthreads();
    float c = csh;
    g[row * DD + t] = c * x + (1.f - c) * hp;
}

// all 4 pair projections in one launch (z: 0=p1a 1=p1b 2=p2a 3=p2b)
__global__ void k_proj(const float* __restrict__ g,
                       const float* __restrict__ WA1, const float* __restrict__ bA1,
                       const float* __restrict__ WB1, const float* __restrict__ bB1,
                       float* __restrict__ p1a, float* __restrict__ p1b,
                       float* __restrict__ p2a, float* __restrict__ p2b) {
    int z = blockIdx.z;
    const float* A; const float* B; const float* bias; float* C; int mt;
    switch (z) {
        case 0: A = g;            B = WA1;           bias = bA1;   C = p1a; mt = R1 / 64; break;
        case 1: A = g;            B = WB1;           bias = bB1;   C = p1b; mt = R1 / 64; break;
        case 2: A = g + (long)R1 * DD; B = WA1 + DD * DD; bias = nullptr; C = p2a; mt = (BB * NN2) / 64; break;
        default:A = g + (long)R1 * DD; B = WB1 + DD * DD; bias = nullptr; C = p2b; mt = (BB * NN2) / 64; break;
    }
    if ((int)blockIdx.y >= mt) return;
    gemm64k(A, DD, B, DD, bias, C, DD, DD, blockIdx.y * 64, blockIdx.x * 64);
}

// Z[b,i,j] = act( b2 + sum_h relu(P1[i,h]+P2[j,h]) * w2[h] ), 32x32 tiles
__global__ void k_zmat(const float* __restrict__ p1a, const float* __restrict__ p1b,
                       const float* __restrict__ p2a, const float* __restrict__ p2b,
                       const float* __restrict__ w2A, const float* __restrict__ w2B,
                       const float* __restrict__ b2A, const float* __restrict__ b2B,
                       float* __restrict__ ZA, float* __restrict__ ZB) {
    __shared__ float P1s[DD][33];
    __shared__ float P2s[DD][33];
    __shared__ float w2s[DD];
    int z = blockIdx.z;
    int b = z >> 1, mlp = z & 1;
    const float* P1 = (mlp ? p1b : p1a) + (long)b * NN1 * DD;
    const float* P2 = (mlp ? p2b : p2a) + (long)b * NN2 * DD;
    const float* w2 = mlp ? w2B : w2A;
    float b2 = mlp ? b2B[0] : b2A[0];
    float* Z = (mlp ? ZB : ZA) + (long)b * NN1 * NN2;
    int i0 = blockIdx.y * 32, j0 = blockIdx.x * 32;
    int tid = threadIdx.x;
    if (tid < DD) w2s[tid] = w2[tid];
    {
        int row = tid >> 3, cb = (tid & 7) * 16;
        #pragma unroll
        for (int q = 0; q < 4; q++) {
            float4 v1 = *(const float4*)&P1[(long)(i0 + row) * DD + cb + q * 4];
            float4 v2 = *(const float4*)&P2[(long)(j0 + row) * DD + cb + q * 4];
            P1s[cb + q * 4 + 0][row] = v1.x; P1s[cb + q * 4 + 1][row] = v1.y;
            P1s[cb + q * 4 + 2][row] = v1.z; P1s[cb + q * 4 + 3][row] = v1.w;
            P2s[cb + q * 4 + 0][row] = v2.x; P2s[cb + q * 4 + 1][row] = v2.y;
            P2s[cb + q * 4 + 2][row] = v2.z; P2s[cb + q * 4 + 3][row] = v2.w;
        }
    }
    __syncthreads();
    int tx = tid & 15, ty = tid >> 4;
    float a00 = 0.f, a01 = 0.f, a10 = 0.f, a11 = 0.f;
    #pragma unroll 4
    for (int k = 0; k < DD; k++) {
        float w = w2s[k];
        float p0 = P1s[k][ty], p1 = P1s[k][ty + 16];
        float q0 = P2s[k][tx], q1 = P2s[k][tx + 16];
        a00 += fmaxf(p0 + q0, 0.f) * w;
        a01 += fmaxf(p0 + q1, 0.f) * w;
        a10 += fmaxf(p1 + q0, 0.f) * w;
        a11 += fmaxf(p1 + q1, 0.f) * w;
    }
    a00 += b2; a01 += b2; a10 += b2; a11 += b2;
    if (mlp == 0) {
        a00 = 1.f / (1.f + __expf(-a00)); a01 = 1.f / (1.f + __expf(-a01));
        a10 = 1.f / (1.f + __expf(-a10)); a11 = 1.f / (1.f + __expf(-a11));
    } else {
        a00 = tanhf(a00) * 0.2f; a01 = tanhf(a01) * 0.2f;
        a10 = tanhf(a10) * 0.2f; a11 = tanhf(a11) * 0.2f;
    }
    Z[(long)(i0 + ty) * NN2 + j0 + tx]           = a00;
    Z[(long)(i0 + ty) * NN2 + j0 + tx + 16]      = a01;
    Z[(long)(i0 + ty + 16) * NN2 + j0 + tx]      = a10;
    Z[(long)(i0 + ty + 16) * NN2 + j0 + tx + 16] = a11;
}

// elementwise physics + per-(b,i) reduction
__global__ void k_phys(const float* __restrict__ ZA, const float* __restrict__ ZB,
                       const float* __restrict__ pos1, const float* __restrict__ pos2,
                       const float* __restrict__ r1, const float* __restrict__ r2,
                       const float* __restrict__ nm1, const float* __restrict__ nm2,
                       const float* __restrict__ A_int, float* __restrict__ part) {
    int b = blockIdx.x >> 7, i = blockIdx.x & 127;
    int t = threadIdx.x;
    float px = pos1[(b * NN1 + i) * 3 + 0];
    float py = pos1[(b * NN1 + i) * 3 + 1];
    float pz = pos1[(b * NN1 + i) * 3 + 2];
    float rr1 = r1[b * NN1 + i];
    float m1  = nm1[b * NN1 + i];
    size_t zbase = (size_t)b * NN1 * NN2 + (size_t)i * NN2;
    size_t abase = (size_t)b * 8 * NN1 * NN2 + (size_t)i * NN2;
    const size_t chw = (size_t)NN1 * NN2;
    float s0 = 0.f, s1 = 0.f, s2 = 0.f, s3 = 0.f;
    for (int j = t; j < NN2; j += 128) {
        float Aw = ZA[zbase + j];
        float Bw = ZB[zbase + j];
        float dx = px - pos2[(b * NN2 + j) * 3 + 0];
        float dy = py - pos2[(b * NN2 + j) * 3 + 1];
        float dz = pz - pos2[(b * NN2 + j) * 3 + 2];
        float dm = sqrtf(dx * dx + dy * dy + dz * dz + 1e-10f);
        if (dm < 0.5f) dm = 1e10f;
        float dm0 = rr1 + r2[b * NN2 + j] + Bw;
        float dm0s = (dm0 < 1e-4f) ? 1.f : dm0;
        float rq = dm0s / dm;
        float rq2 = rq * rq;
        float r6 = rq2 * rq2 * rq2;
        float evdw = fminf(r6 * r6 - 2.f * r6, 100.f);
        float Aamp = Aw * (0.0356f - 0.0178f) + 0.0178f;
        s0 += Aamp * evdw * m1 * nm2[b * NN2 + j];
        float dmd = dm - dm0;
        float a1 = A_int[abase + 1 * chw + j];
        float a7 = A_int[abase + 7 * chw + j];
        float a6 = A_int[abase + 6 * chw + j];
        s1 += fminf(fmaxf(dmd * a1 * (-1.f / 0.7f), 0.f), 1.f);
        s2 += fminf(fmaxf(dmd * a7 * (-1.f / 0.7f), 0.f), 1.f);
        s3 += fminf(fmaxf((1.5f - dmd) * a6, 0.f), 1.f);
    }
    #pragma unroll
    for (int o = 16; o > 0; o >>= 1) {
        s0 += __shfl_down_sync(0xffffffffu, s0, o);
        s1 += __shfl_down_sync(0xffffffffu, s1, o);
        s2 += __shfl_down_sync(0xffffffffu, s2, o);
        s3 += __shfl_down_sync(0xffffffffu, s3, o);
    }
    __shared__ float acc[4][4];
    int lane = t & 31, w = t >> 5;
    if (lane == 0) { acc[w][0] = s0; acc[w][1] = s1; acc[w][2] = s2; acc[w][3] = s3; }
    __syncthreads();
    if (t < 4)
        part[((size_t)b * NN1 + i) * 4 + t] = acc[0][t] + acc[1][t] + acc[2][t] + acc[3][t];
}

__global__ void k_final(const float* __restrict__ part, const float* __restrict__ rotor,
                        const float* __restrict__ duff, const float* __restrict__ hbc,
                        const float* __restrict__ hyc, const float* __restrict__ vdc,
                        const float* __restrict__ rtc, float* __restrict__ out) {
    int b = blockIdx.x, t = threadIdx.x;
    size_t base = ((size_t)b * NN1 + t) * 4;
    float v0 = part[base + 0], v1 = part[base + 1], v2 = part[base + 2], v3 = part[base + 3];
    #pragma unroll
    for (int o = 16; o > 0; o >>= 1) {
        v0 += __shfl_down_sync(0xffffffffu, v0, o);
        v1 += __shfl_down_sync(0xffffffffu, v1, o);
        v2 += __shfl_down_sync(0xffffffffu, v2, o);
        v3 += __shfl_down_sync(0xffffffffu, v3, o);
    }
    __shared__ float red[4][4];
    if ((t & 31) == 0) {
        int w = t >> 5;
        red[w][0] = v0; red[w][1] = v1; red[w][2] = v2; red[w][3] = v3;
    }
    __syncthreads();
    if (t == 0) {
        float s0 = red[0][0] + red[1][0] + red[2][0] + red[3][0];
        float s1 = red[0][1] + red[1][1] + red[2][1] + red[3][1];
        float s2 = red[0][2] + red[1][2] + red[2][2] + red[3][2];
        float s3 = red[0][3] + red[1][3] + red[2][3] + red[3][3];
        float hb = -hbc[0] * hbc[0];
        float hy = -hyc[0] * hyc[0];
        float inv = 1.f / (1.f + rtc[0] * rtc[0] * rotor[b]);
        out[b * 5 + 0] = s0 * inv;
        out[b * 5 + 1] = s1 * hb * inv;
        out[b * 5 + 2] = s2 * hb * inv;
        out[b * 5 + 3] = s3 * hy * inv;
        out[b * 5 + 4] = duff[b] * vdc[0] * vdc[0] * inv;
    }
}

// ---------------- host side ----------------
extern "C" void kernel_launch(void* const* d_in, const int* in_sizes, int n_in,
                              void* d_out, int out_size) {
    (void)in_sizes; (void)n_in; (void)out_size;
    const float* h1      = (const float*)d_in[0];
    const float* adj1    = (const float*)d_in[1];
    const float* h2      = (const float*)d_in[2];
    const float* adj2    = (const float*)d_in[3];
    const float* A_int   = (const float*)d_in[4];
    const float* pos1    = (const float*)d_in[5];
    const float* pos2    = (const float*)d_in[6];
    const float* rotor   = (const float*)d_in[7];
    const float* vdw_r1  = (const float*)d_in[8];
    const float* vdw_r2  = (const float*)d_in[9];
    const float* duff    = (const float*)d_in[10];
    const float* nm1     = (const float*)d_in[11];
    const float* nm2     = (const float*)d_in[12];
    const float* node_W  = (const float*)d_in[13];
    const float* gat_W   = (const float*)d_in[14];
    const float* gat_b   = (const float*)d_in[15];
    const float* gat_A   = (const float*)d_in[16];
    const float* gate_W  = (const float*)d_in[17];
    const float* gate_b  = (const float*)d_in[18];
    const float* vdwA_W1 = (const float*)d_in[19];
    const float* vdwA_b1 = (const float*)d_in[20];
    const float* vdwA_W2 = (const float*)d_in[21];
    const float* vdwA_b2 = (const float*)d_in[22];
    const float* vdwB_W1 = (const float*)d_in[23];
    const float* vdwB_b1 = (const float*)d_in[24];
    const float* vdwB_W2 = (const float*)d_in[25];
    const float* vdwB_b2 = (const float*)d_in[26];
    const float* hbond   = (const float*)d_in[27];
    const float* hydro   = (const float*)d_in[28];
    const float* vdwc    = (const float*)d_in[29];
    const float* rotc    = (const float*)d_in[30];
    float* out = (float*)d_out;

    float *gp, *hp_, *hAp, *hpart, *e2p, *e1p, *wap, *bap;
    float *p1a, *p1b, *p2a, *p2b, *zap, *zbp, *partp;
    float2* statp;
    cudaGetSymbolAddress((void**)&gp,  g_g);
    cudaGetSymbolAddress((void**)&hp_, g_h);
    cudaGetSymbolAddress((void**)&hAp, g_hA);
    cudaGetSymbolAddress((void**)&hpart, g_hpart);
    cudaGetSymbolAddress((void**)&e2p, g_e2);
    cudaGetSymbolAddress((void**)&e1p, g_e1);
    cudaGetSymbolAddress((void**)&statp, g_stat);
    cudaGetSymbolAddress((void**)&wap, g_WA);
    cudaGetSymbolAddress((void**)&bap, g_bA);
    cudaGetSymbolAddress((void**)&p1a, g_P1A);
    cudaGetSymbolAddress((void**)&p1b, g_P1B);
    cudaGetSymbolAddress((void**)&p2a, g_P2A);
    cudaGetSymbolAddress((void**)&p2b, g_P2B);
    cudaGetSymbolAddress((void**)&zap, g_ZA);
    cudaGetSymbolAddress((void**)&zbp, g_ZB);
    cudaGetSymbolAddress((void**)&partp, g_part);

    // merged prologue + embedding
    k_pre<<<15, 256>>>(gat_W, gat_A, gat_b, wap, bap);
    k_embed_both<<<MROWS, DD>>>(h1, h2, node_W, gp);

    for (int l = 0; l < 3; l++) {
        const float* W  = gat_W  + (size_t)l * DD * DD;
        const float* bW = gat_b  + (size_t)l * DD;
        const float* WA = wap    + (size_t)l * DD * DD;
        const float* bA = bap    + (size_t)l * DD;
        const float* gW = gate_W + (size_t)l * 2 * DD;
        const float* gb = gate_b + l;
        k_dual<<<dim3(4, MROWS / 64, 1), 256>>>(gp, W, bW, WA, bA, hp_, hAp);
        k_ntsym<<<dim3(8, 8, 16), 256>>>(hp_, hAp, adj2, e2p, adj1, e1p);
        k_rowstat<<<BB * NN2 + BB * NN1, 128>>>(e2p, e1p, statp);
        k_hp<<<dim3(8, 8, 16), 256>>>(e2p, e1p, statp, hp_, hpart);
        k_gate<<<MROWS, DD>>>(gp, hpart, gW, gb);
    }

    // pair projections (one launch)
    k_proj<<<dim3(2, 64, 4), 256>>>(gp, vdwA_W1, vdwA_b1, vdwB_W1, vdwB_b1,
                                    p1a, p1b, p2a, p2b);
    // pair bilinear-relu MLP matrices
    k_zmat<<<dim3(16, 4, 16), 256>>>(p1a, p1b, p2a, p2b, vdwA_W2, vdwB_W2,
                                     vdwA_b2, vdwB_b2, zap, zbp);
    // physics + reductions
    k_phys<<<BB * NN1, 128>>>(zap, zbp, pos1, pos2, vdw_r1, vdw_r2, nm1, nm2,
                              A_int, partp);
    k_final<<<BB, 128>>>(partp, rotor, duff, hbond, hydro, vdwc, rotc, out);
}

// round 15
// speedup vs baseline: 1.0682x; 1.0281x over previous
#include <cuda_runtime.h>
#include <math.h>

#define BB  8
#define NN1 128
#define NN2 512
#define DD  128
#define MROWS (BB * (NN1 + NN2))   // 5120 combined rows
#define R1   (BB * NN1)            // 1024 graph-1 rows

// ---------------- static device scratch ----------------
__device__ float g_g  [MROWS * DD];
__device__ float g_h  [MROWS * DD];
__device__ float g_hA [MROWS * DD];
__device__ float g_hpart[4 * MROWS * DD];   // split-K partials for hp
__device__ float g_e2 [BB * NN2 * NN2];     // masked symmetric logits (graph2)
__device__ float g_e1 [BB * NN1 * NN1];
__device__ float2 g_stat[BB * NN2 + BB * NN1];  // per-row (max, 1/sum)
__device__ float g_WA [3 * DD * DD];
__device__ float g_bA [3 * DD];
__device__ float g_P1A[BB * NN1 * DD];
__device__ float g_P1B[BB * NN1 * DD];
__device__ float g_P2A[BB * NN2 * DD];
__device__ float g_P2B[BB * NN2 * DD];
__device__ float g_ZA [BB * NN1 * NN2];
__device__ float g_ZB [BB * NN1 * NN2];
__device__ float g_part[BB * NN1 * 4];

// ---------------- packed f32x2 helpers (Blackwell FFMA2) ----------------
__device__ __forceinline__ unsigned long long pk2(float x, float y) {
    unsigned long long r;
    asm("mov.b64 %0, {%1, %2};" : "=l"(r) : "f"(x), "f"(y));
    return r;
}
__device__ __forceinline__ unsigned long long dup2(float x) {
    unsigned long long r;
    asm("mov.b64 %0, {%1, %1};" : "=l"(r) : "f"(x));
    return r;
}
__device__ __forceinline__ void fma2(unsigned long long& acc, unsigned long long a,
                                     unsigned long long b) {
    asm("fma.rn.f32x2 %0, %1, %2, %0;" : "+l"(acc) : "l"(a), "l"(b));
}
__device__ __forceinline__ float2 unpk(unsigned long long v) {
    float2 r;
    asm("mov.b64 {%0, %1}, %2;" : "=f"(r.x), "=f"(r.y) : "l"(v));
    return r;
}

// ---------------- generic 64x64 NN GEMM body with register prefetch ----------------
__device__ __forceinline__ void gemm64k(const float* __restrict__ A, int lda,
                                        const float* __restrict__ B, int ldb,
                                        const float* __restrict__ bias,
                                        float* __restrict__ C, int ldc,
                                        int K, int m0, int n0) {
    __shared__ float As[16][68];
    __shared__ float Bs[16][68];
    int tid = threadIdx.x;
    int tx = tid & 15, ty = tid >> 4;
    int lm = tid >> 2, lkq = (tid & 3) * 4;
    int lk = tid >> 4, ln = (tid & 15) * 4;
    unsigned long long accp[4][2] = {};
    float4 a_pre = *(const float4*)&A[(long)(m0 + lm) * lda + lkq];
    float4 b_pre = *(const float4*)&B[(long)lk * ldb + n0 + ln];
    for (int k0 = 0; k0 < K; k0 += 16) {
        As[lkq + 0][lm] = a_pre.x; As[lkq + 1][lm] = a_pre.y;
        As[lkq + 2][lm] = a_pre.z; As[lkq + 3][lm] = a_pre.w;
        *(float4*)&Bs[lk][ln] = b_pre;
        __syncthreads();
        if (k0 + 16 < K) {
            a_pre = *(const float4*)&A[(long)(m0 + lm) * lda + k0 + 16 + lkq];
            b_pre = *(const float4*)&B[(long)(k0 + 16 + lk) * ldb + n0 + ln];
        }
        #pragma unroll
        for (int k = 0; k < 16; k++) {
            float4 av = *(float4*)&As[k][ty * 4];
            float4 bv = *(float4*)&Bs[k][tx * 4];
            unsigned long long b01 = pk2(bv.x, bv.y);
            unsigned long long b23 = pk2(bv.z, bv.w);
            float am[4] = {av.x, av.y, av.z, av.w};
            #pragma unroll
            for (int i = 0; i < 4; i++) {
                unsigned long long a2 = dup2(am[i]);
                fma2(accp[i][0], a2, b01);
                fma2(accp[i][1], a2, b23);
            }
        }
        __syncthreads();
    }
    #pragma unroll
    for (int i = 0; i < 4; i++) {
        int m = m0 + ty * 4 + i;
        int n = n0 + tx * 4;
        float2 c01 = unpk(accp[i][0]);
        float2 c23 = unpk(accp[i][1]);
        float4 v;
        v.x = c01.x + (bias ? bias[n + 0] : 0.f);
        v.y = c01.y + (bias ? bias[n + 1] : 0.f);
        v.z = c23.x + (bias ? bias[n + 2] : 0.f);
        v.w = c23.y + (bias ? bias[n + 3] : 0.f);
        *(float4*)&C[(long)m * ldc + n] = v;
    }
}

// merged prologue: blocks 0..11 WA[l]=W@A tiles; blocks 12..14 bA[l]=b@A
__global__ void k_pre(const float* __restrict__ W, const float* __restrict__ A,
                      const float* __restrict__ b, float* __restrict__ WA,
                      float* __restrict__ bA) {
    int bx = blockIdx.x;
    if (bx < 12) {
        int l = bx >> 2, t = bx & 3;
        gemm64k(W + (long)l * DD * DD, DD, A + (long)l * DD * DD, DD, nullptr,
                WA + (long)l * DD * DD, DD, DD, (t >> 1) * 64, (t & 1) * 64);
    } else {
        int l = bx - 12, n = threadIdx.x;
        if (n < DD) {
            float acc = 0.f;
            #pragma unroll 8
            for (int k = 0; k < DD; k++)
                acc += b[l * DD + k] * A[((long)l * DD + k) * DD + n];
            bA[l * DD + n] = acc;
        }
    }
}

// embedding for both graphs
__global__ void k_embed_both(const float* __restrict__ X1, const float* __restrict__ X2,
                             const float* __restrict__ W, float* __restrict__ Y) {
    int bn = blockIdx.x;
    const float* src = (bn < R1) ? X1 + (size_t)bn * 54
                                 : X2 + (size_t)(bn - R1) * 54;
    __shared__ float xs[54];
    if (threadIdx.x < 54) xs[threadIdx.x] = src[threadIdx.x];
    __syncthreads();
    int d = threadIdx.x;
    float acc = 0.f;
    #pragma unroll
    for (int l = 0; l < 54; l++) acc += xs[l] * W[l * DD + d];
    Y[(size_t)bn * DD + d] = acc;
}

// h = g@W + b ; hA = g@WA + bA  (one launch, 5120 rows)
__global__ void k_dual(const float* __restrict__ g, const float* __restrict__ W,
                       const float* __restrict__ b, const float* __restrict__ WA,
                       const float* __restrict__ bA, float* __restrict__ h,
                       float* __restrict__ hA) {
    int xi = blockIdx.x;
    const float* B; const float* bias; float* C; int n0;
    if (xi < 2) { B = W;  bias = b;  C = h;  n0 = xi * 64; }
    else        { B = WA; bias = bA; C = hA; n0 = (xi - 2) * 64; }
    gemm64k(g, DD, B, DD, bias, C, DD, DD, blockIdx.y * 64, n0);
}

// masked symmetric logits: L[m,n] = adj>0 ? (hA_m.h_n + h_m.hA_n) : -9e15
// full-tile, with register prefetch of the 4 staged operand streams
__global__ void k_ntsym(const float* __restrict__ h, const float* __restrict__ hA,
                        const float* __restrict__ adj2, float* __restrict__ e2,
                        const float* __restrict__ adj1, float* __restrict__ e1) {
    int z = blockIdx.z;
    int N; const float* Hb; const float* Ab; const float* Adj; float* Cb;
    if (z < 8) {
        N = NN2;
        Hb = h  + ((long)R1 + (long)z * NN2) * DD;
        Ab = hA + ((long)R1 + (long)z * NN2) * DD;
        Adj = adj2 + (long)z * NN2 * NN2;
        Cb = e2 + (long)z * NN2 * NN2;
    } else {
        if (blockIdx.x >= 2 || blockIdx.y >= 2) return;
        N = NN1;
        Hb = h  + (long)(z - 8) * NN1 * DD;
        Ab = hA + (long)(z - 8) * NN1 * DD;
        Adj = adj1 + (long)(z - 8) * NN1 * NN1;
        Cb = e1 + (long)(z - 8) * NN1 * NN1;
    }
    __shared__ float AsA[16][68];
    __shared__ float AsH[16][68];
    __shared__ float BsH[16][68];
    __shared__ float BsA[16][68];
    int m0 = blockIdx.y * 64, n0 = blockIdx.x * 64;
    int tid = threadIdx.x;
    int tx = tid & 15, ty = tid >> 4;
    int lm = tid >> 2, lkq = (tid & 3) * 4;
    unsigned long long accp[4][2] = {};
    long rowM = (long)(m0 + lm) * DD;
    long rowN = (long)(n0 + lm) * DD;
    float4 pA  = *(const float4*)&Ab[rowM + lkq];
    float4 pH  = *(const float4*)&Hb[rowM + lkq];
    float4 pbH = *(const float4*)&Hb[rowN + lkq];
    float4 pbA = *(const float4*)&Ab[rowN + lkq];
    for (int k0 = 0; k0 < DD; k0 += 16) {
        AsA[lkq + 0][lm] = pA.x;  AsA[lkq + 1][lm] = pA.y;
        AsA[lkq + 2][lm] = pA.z;  AsA[lkq + 3][lm] = pA.w;
        AsH[lkq + 0][lm] = pH.x;  AsH[lkq + 1][lm] = pH.y;
        AsH[lkq + 2][lm] = pH.z;  AsH[lkq + 3][lm] = pH.w;
        BsH[lkq + 0][lm] = pbH.x; BsH[lkq + 1][lm] = pbH.y;
        BsH[lkq + 2][lm] = pbH.z; BsH[lkq + 3][lm] = pbH.w;
        BsA[lkq + 0][lm] = pbA.x; BsA[lkq + 1][lm] = pbA.y;
        BsA[lkq + 2][lm] = pbA.z; BsA[lkq + 3][lm] = pbA.w;
        __syncthreads();
        if (k0 + 16 < DD) {
            pA  = *(const float4*)&Ab[rowM + k0 + 16 + lkq];
            pH  = *(const float4*)&Hb[rowM + k0 + 16 + lkq];
            pbH = *(const float4*)&Hb[rowN + k0 + 16 + lkq];
            pbA = *(const float4*)&Ab[rowN + k0 + 16 + lkq];
        }
        #pragma unroll
        for (int k = 0; k < 16; k++) {
            float4 avA = *(float4*)&AsA[k][ty * 4];
            float4 avH = *(float4*)&AsH[k][ty * 4];
            float4 bvH = *(float4*)&BsH[k][tx * 4];
            float4 bvA = *(float4*)&BsA[k][tx * 4];
            unsigned long long h01 = pk2(bvH.x, bvH.y);
            unsigned long long h23 = pk2(bvH.z, bvH.w);
            unsigned long long A01 = pk2(bvA.x, bvA.y);
            unsigned long long A23 = pk2(bvA.z, bvA.w);
            float amA[4] = {avA.x, avA.y, avA.z, avA.w};
            float amH[4] = {avH.x, avH.y, avH.z, avH.w};
            #pragma unroll
            for (int i = 0; i < 4; i++) {
                unsigned long long dA = dup2(amA[i]);
                unsigned long long dH = dup2(amH[i]);
                fma2(accp[i][0], dA, h01);
                fma2(accp[i][1], dA, h23);
                fma2(accp[i][0], dH, A01);
                fma2(accp[i][1], dH, A23);
            }
        }
        __syncthreads();
    }
    #pragma unroll
    for (int i = 0; i < 4; i++) {
        int m = m0 + ty * 4 + i, n = n0 + tx * 4;
        float2 c01 = unpk(accp[i][0]);
        float2 c23 = unpk(accp[i][1]);
        float4 ad = *(const float4*)&Adj[(long)m * N + n];
        float4 v;
        v.x = (ad.x > 0.f) ? c01.x : -9e15f;
        v.y = (ad.y > 0.f) ? c01.y : -9e15f;
        v.z = (ad.z > 0.f) ? c23.x : -9e15f;
        v.w = (ad.w > 0.f) ? c23.y : -9e15f;
        *(float4*)&Cb[(long)m * N + n] = v;
    }
}

// per-row softmax stats: stat[row] = (max, 1/sum_exp). rows 0..4095: graph2; then graph1.
__global__ void k_rowstat(const float* __restrict__ e2, const float* __restrict__ e1,
                          float2* __restrict__ stat) {
    int bx = blockIdx.x;
    int t = threadIdx.x;
    int lane = t & 31, w = t >> 5;
    __shared__ float red[4];
    __shared__ float bcast;
    if (bx < BB * NN2) {
        const float* L = e2 + (long)bx * NN2;
        float v[4];
        float m = -3.4e38f;
        #pragma unroll
        for (int q = 0; q < 4; q++) { v[q] = L[t + 128 * q]; m = fmaxf(m, v[q]); }
        #pragma unroll
        for (int o = 16; o > 0; o >>= 1) m = fmaxf(m, __shfl_xor_sync(0xffffffffu, m, o));
        if (lane == 0) red[w] = m;
        __syncthreads();
        if (t == 0) bcast = fmaxf(fmaxf(red[0], red[1]), fmaxf(red[2], red[3]));
        __syncthreads();
        m = bcast;
        float s = 0.f;
        #pragma unroll
        for (int q = 0; q < 4; q++) s += __expf(v[q] - m);
        #pragma unroll
        for (int o = 16; o > 0; o >>= 1) s += __shfl_xor_sync(0xffffffffu, s, o);
        if (lane == 0) red[w] = s;
        __syncthreads();
        if (t == 0) {
            float ss = red[0] + red[1] + red[2] + red[3];
            stat[bx] = make_float2(m, 1.f / ss);
        }
    } else {
        int row = bx - BB * NN2;
        const float* L = e1 + (long)row * NN1;
        float v = L[t];
        float m = v;
        #pragma unroll
        for (int o = 16; o > 0; o >>= 1) m = fmaxf(m, __shfl_xor_sync(0xffffffffu, m, o));
        if (lane == 0) red[w] = m;
        __syncthreads();
        if (t == 0) bcast = fmaxf(fmaxf(red[0], red[1]), fmaxf(red[2], red[3]));
        __syncthreads();
        m = bcast;
        float s = __expf(v - m);
        #pragma unroll
        for (int o = 16; o > 0; o >>= 1) s += __shfl_xor_sync(0xffffffffu, s, o);
        if (lane == 0) red[w] = s;
        __syncthreads();
        if (t == 0) {
            float ss = red[0] + red[1] + red[2] + red[3];
            stat[bx] = make_float2(m, 1.f / ss);
        }
    }
}

// split-K hp GEMM (TN: hp = R^T @ h) with row-softmax applied on load + prefetch
__global__ void k_hp(const float* __restrict__ e2, const float* __restrict__ e1,
                     const float2* __restrict__ stat, const float* __restrict__ h,
                     float* __restrict__ part) {
    int z = blockIdx.z;
    const float* A; int lda, K, statbase;
    const float* B; float* C; int m0, n0;
    if (z < 8) {
        int chunk = blockIdx.x >> 1, nt = blockIdx.x & 1;
        A = e2 + (long)z * NN2 * NN2 + (long)chunk * 128 * NN2;
        lda = NN2; K = 128;
        statbase = z * NN2 + chunk * 128;
        B = h + ((long)R1 + (long)z * NN2 + chunk * 128) * DD;
        C = part + (long)chunk * MROWS * DD + ((long)R1 + (long)z * NN2) * DD;
        m0 = blockIdx.y * 64; n0 = nt * 64;
    } else {
        if (blockIdx.x >= 2 || blockIdx.y >= 2) return;
        A = e1 + (long)(z - 8) * NN1 * NN1;
        lda = NN1; K = NN1;
        statbase = BB * NN2 + (z - 8) * NN1;
        B = h + (long)(z - 8) * NN1 * DD;
        C = part + (long)(z - 8) * NN1 * DD;
        m0 = blockIdx.y * 64; n0 = blockIdx.x * 64;
    }
    __shared__ float As[16][68];
    __shared__ float Bs[16][68];
    int tid = threadIdx.x;
    int tx = tid & 15, ty = tid >> 4;
    int lk = tid >> 4, lq = (tid & 15) * 4;
    unsigned long long accp[4][2] = {};
    float2 st_pre = stat[statbase + lk];
    float4 a_pre = *(const float4*)&A[(long)lk * lda + m0 + lq];
    float4 b_pre = *(const float4*)&B[(long)lk * DD + n0 + lq];
    for (int k0 = 0; k0 < K; k0 += 16) {
        float4 a4;
        a4.x = __expf(a_pre.x - st_pre.x) * st_pre.y;
        a4.y = __expf(a_pre.y - st_pre.x) * st_pre.y;
        a4.z = __expf(a_pre.z - st_pre.x) * st_pre.y;
        a4.w = __expf(a_pre.w - st_pre.x) * st_pre.y;
        *(float4*)&As[lk][lq] = a4;
        *(float4*)&Bs[lk][lq] = b_pre;
        __syncthreads();
        if (k0 + 16 < K) {
            st_pre = stat[statbase + k0 + 16 + lk];
            a_pre = *(const float4*)&A[(long)(k0 + 16 + lk) * lda + m0 + lq];
            b_pre = *(const float4*)&B[(long)(k0 + 16 + lk) * DD + n0 + lq];
        }
        #pragma unroll
        for (int k = 0; k < 16; k++) {
            float4 av = *(float4*)&As[k][ty * 4];
            float4 bv = *(float4*)&Bs[k][tx * 4];
            unsigned long long b01 = pk2(bv.x, bv.y);
            unsigned long long b23 = pk2(bv.z, bv.w);
            float am[4] = {av.x, av.y, av.z, av.w};
            #pragma unroll
            for (int i = 0; i < 4; i++) {
                unsigned long long a2 = dup2(am[i]);
                fma2(accp[i][0], a2, b01);
                fma2(accp[i][1], a2, b23);
            }
        }
        __syncthreads();
    }
    #pragma unroll
    for (int i = 0; i < 4; i++) {
        int m = m0 + ty * 4 + i, n = n0 + tx * 4;
        float2 c01 = unpk(accp[i][0]);
        float2 c23 = unpk(accp[i][1]);
        float4 v = {c01.x, c01.y, c23.x, c23.y};
        *(float4*)&C[(long)m * DD + n] = v;
    }
}

// gate: hp = relu(sum chunks); c = sigmoid(g.gW1 + hp.gW2 + gb); g = c*g + (1-c)*hp
__global__ void k_gate(float* __restrict__ g, const float* __restrict__ part,
                       const float* __restrict__ gW, const float* __restrict__ gb) {
    long row = blockIdx.x;
    int t = threadIdx.x;
    float hp = part[row * DD + t];
    if (row >= R1) {
        hp += part[(long)1 * MROWS * DD + row * DD + t];
        hp += part[(long)2 * MROWS * DD + row * DD + t];
        hp += part[(long)3 * MROWS * DD + row * DD + t];
    }
    hp = fmaxf(hp, 0.f);
    float x = g[row * DD + t];
    float v = x * gW[t] + hp * gW[DD + t];
    #pragma unroll
    for (int o = 16; o > 0; o >>= 1) v += __shfl_down_sync(0xffffffffu, v, o);
    __shared__ float red[4];
    __shared__ float csh;
    if ((t & 31) == 0) red[t >> 5] = v;
    __syncthreads();
    if (t == 0) {
        float s = red[0] + red[1] + red[2] + red[3] + gb[0];
        csh = 1.f / (1.f + __expf(-s));
    }
    __syncthreads();
    float c = csh;
    g[row * DD + t] = c * x + (1.f - c) * hp;
}

// all 4 pair projections in one launch (z: 0=p1a 1=p1b 2=p2a 3=p2b)
__global__ void k_proj(const float* __restrict__ g,
                       const float* __restrict__ WA1, const float* __restrict__ bA1,
                       const float* __restrict__ WB1, const float* __restrict__ bB1,
                       float* __restrict__ p1a, float* __restrict__ p1b,
                       float* __restrict__ p2a, float* __restrict__ p2b) {
    int z = blockIdx.z;
    const float* A; const float* B; const float* bias; float* C; int mt;
    switch (z) {
        case 0: A = g;            B = WA1;           bias = bA1;   C = p1a; mt = R1 / 64; break;
        case 1: A = g;            B = WB1;           bias = bB1;   C = p1b; mt = R1 / 64; break;
        case 2: A = g + (long)R1 * DD; B = WA1 + DD * DD; bias = nullptr; C = p2a; mt = (BB * NN2) / 64; break;
        default:A = g + (long)R1 * DD; B = WB1 + DD * DD; bias = nullptr; C = p2b; mt = (BB * NN2) / 64; break;
    }
    if ((int)blockIdx.y >= mt) return;
    gemm64k(A, DD, B, DD, bias, C, DD, DD, blockIdx.y * 64, blockIdx.x * 64);
}

// Z[b,i,j] = act( b2 + sum_h relu(P1[i,h]+P2[j,h]) * w2[h] ), 32x32 tiles
__global__ void k_zmat(const float* __restrict__ p1a, const float* __restrict__ p1b,
                       const float* __restrict__ p2a, const float* __restrict__ p2b,
                       const float* __restrict__ w2A, const float* __restrict__ w2B,
                       const float* __restrict__ b2A, const float* __restrict__ b2B,
                       float* __restrict__ ZA, float* __restrict__ ZB) {
    __shared__ float P1s[DD][33];
    __shared__ float P2s[DD][33];
    __shared__ float w2s[DD];
    int z = blockIdx.z;
    int b = z >> 1, mlp = z & 1;
    const float* P1 = (mlp ? p1b : p1a) + (long)b * NN1 * DD;
    const float* P2 = (mlp ? p2b : p2a) + (long)b * NN2 * DD;
    const float* w2 = mlp ? w2B : w2A;
    float b2 = mlp ? b2B[0] : b2A[0];
    float* Z = (mlp ? ZB : ZA) + (long)b * NN1 * NN2;
    int i0 = blockIdx.y * 32, j0 = blockIdx.x * 32;
    int tid = threadIdx.x;
    if (tid < DD) w2s[tid] = w2[tid];
    {
        int row = tid >> 3, cb = (tid & 7) * 16;
        #pragma unroll
        for (int q = 0; q < 4; q++) {
            float4 v1 = *(const float4*)&P1[(long)(i0 + row) * DD + cb + q * 4];
            float4 v2 = *(const float4*)&P2[(long)(j0 + row) * DD + cb + q * 4];
            P1s[cb + q * 4 + 0][row] = v1.x; P1s[cb + q * 4 + 1][row] = v1.y;
            P1s[cb + q * 4 + 2][row] = v1.z; P1s[cb + q * 4 + 3][row] = v1.w;
            P2s[cb + q * 4 + 0][row] = v2.x; P2s[cb + q * 4 + 1][row] = v2.y;
            P2s[cb + q * 4 + 2][row] = v2.z; P2s[cb + q * 4 + 3][row] = v2.w;
        }
    }
    __syncthreads();
    int tx = tid & 15, ty = tid >> 4;
    float a00 = 0.f, a01 = 0.f, a10 = 0.f, a11 = 0.f;
    #pragma unroll 4
    for (int k = 0; k < DD; k++) {
        float w = w2s[k];
        float p0 = P1s[k][ty], p1 = P1s[k][ty + 16];
        float q0 = P2s[k][tx], q1 = P2s[k][tx + 16];
        a00 += fmaxf(p0 + q0, 0.f) * w;
        a01 += fmaxf(p0 + q1, 0.f) * w;
        a10 += fmaxf(p1 + q0, 0.f) * w;
        a11 += fmaxf(p1 + q1, 0.f) * w;
    }
    a00 += b2; a01 += b2; a10 += b2; a11 += b2;
    if (mlp == 0) {
        a00 = 1.f / (1.f + __expf(-a00)); a01 = 1.f / (1.f + __expf(-a01));
        a10 = 1.f / (1.f + __expf(-a10)); a11 = 1.f / (1.f + __expf(-a11));
    } else {
        a00 = tanhf(a00) * 0.2f; a01 = tanhf(a01) * 0.2f;
        a10 = tanhf(a10) * 0.2f; a11 = tanhf(a11) * 0.2f;
    }
    Z[(long)(i0 + ty) * NN2 + j0 + tx]           = a00;
    Z[(long)(i0 + ty) * NN2 + j0 + tx + 16]      = a01;
    Z[(long)(i0 + ty + 16) * NN2 + j0 + tx]      = a10;
    Z[(long)(i0 + ty + 16) * NN2 + j0 + tx + 16] = a11;
}

// elementwise physics + per-(b,i) reduction
__global__ void k_phys(const float* __restrict__ ZA, const float* __restrict__ ZB,
                       const float* __restrict__ pos1, const float* __restrict__ pos2,
                       const float* __restrict__ r1, const float* __restrict__ r2,
                       const float* __restrict__ nm1, const float* __restrict__ nm2,
                       const float* __restrict__ A_int, float* __restrict__ part) {
    int b = blockIdx.x >> 7, i = blockIdx.x & 127;
    int t = threadIdx.x;
    float px = pos1[(b * NN1 + i) * 3 + 0];
    float py = pos1[(b * NN1 + i) * 3 + 1];
    float pz = pos1[(b * NN1 + i) * 3 + 2];
    float rr1 = r1[b * NN1 + i];
    float m1  = nm1[b * NN1 + i];
    size_t zbase = (size_t)b * NN1 * NN2 + (size_t)i * NN2;
    size_t abase = (size_t)b * 8 * NN1 * NN2 + (size_t)i * NN2;
    const size_t chw = (size_t)NN1 * NN2;
    float s0 = 0.f, s1 = 0.f, s2 = 0.f, s3 = 0.f;
    for (int j = t; j < NN2; j += 128) {
        float Aw = ZA[zbase + j];
        float Bw = ZB[zbase + j];
        float dx = px - pos2[(b * NN2 + j) * 3 + 0];
        float dy = py - pos2[(b * NN2 + j) * 3 + 1];
        float dz = pz - pos2[(b * NN2 + j) * 3 + 2];
        float dm = sqrtf(dx * dx + dy * dy + dz * dz + 1e-10f);
        if (dm < 0.5f) dm = 1e10f;
        float dm0 = rr1 + r2[b * NN2 + j] + Bw;
        float dm0s = (dm0 < 1e-4f) ? 1.f : dm0;
        float rq = dm0s / dm;
        float rq2 = rq * rq;
        float r6 = rq2 * rq2 * rq2;
        float evdw = fminf(r6 * r6 - 2.f * r6, 100.f);
        float Aamp = Aw * (0.0356f - 0.0178f) + 0.0178f;
        s0 += Aamp * evdw * m1 * nm2[b * NN2 + j];
        float dmd = dm - dm0;
        float a1 = A_int[abase + 1 * chw + j];
        float a7 = A_int[abase + 7 * chw + j];
        float a6 = A_int[abase + 6 * chw + j];
        s1 += fminf(fmaxf(dmd * a1 * (-1.f / 0.7f), 0.f), 1.f);
        s2 += fminf(fmaxf(dmd * a7 * (-1.f / 0.7f), 0.f), 1.f);
        s3 += fminf(fmaxf((1.5f - dmd) * a6, 0.f), 1.f);
    }
    #pragma unroll
    for (int o = 16; o > 0; o >>= 1) {
        s0 += __shfl_down_sync(0xffffffffu, s0, o);
        s1 += __shfl_down_sync(0xffffffffu, s1, o);
        s2 += __shfl_down_sync(0xffffffffu, s2, o);
        s3 += __shfl_down_sync(0xffffffffu, s3, o);
    }
    __shared__ float acc[4][4];
    int lane = t & 31, w = t >> 5;
    if (lane == 0) { acc[w][0] = s0; acc[w][1] = s1; acc[w][2] = s2; acc[w][3] = s3; }
    __syncthreads();
    if (t < 4)
        part[((size_t)b * NN1 + i) * 4 + t] = acc[0][t] + acc[1][t] + acc[2][t] + acc[3][t];
}

__global__ void k_final(const float* __restrict__ part, const float* __restrict__ rotor,
                        const float* __restrict__ duff, const float* __restrict__ hbc,
                        const float* __restrict__ hyc, const float* __restrict__ vdc,
                        const float* __restrict__ rtc, float* __restrict__ out) {
    int b = blockIdx.x, t = threadIdx.x;
    size_t base = ((size_t)b * NN1 + t) * 4;
    float v0 = part[base + 0], v1 = part[base + 1], v2 = part[base + 2], v3 = part[base + 3];
    #pragma unroll
    for (int o = 16; o > 0; o >>= 1) {
        v0 += __shfl_down_sync(0xffffffffu, v0, o);
        v1 += __shfl_down_sync(0xffffffffu, v1, o);
        v2 += __shfl_down_sync(0xffffffffu, v2, o);
        v3 += __shfl_down_sync(0xffffffffu, v3, o);
    }
    __shared__ float red[4][4];
    if ((t & 31) == 0) {
        int w = t >> 5;
        red[w][0] = v0; red[w][1] = v1; red[w][2] = v2; red[w][3] = v3;
    }
    __syncthreads();
    if (t == 0) {
        float s0 = red[0][0] + red[1][0] + red[2][0] + red[3][0];
        float s1 = red[0][1] + red[1][1] + red[2][1] + red[3][1];
        float s2 = red[0][2] + red[1][2] + red[2][2] + red[3][2];
        float s3 = red[0][3] + red[1][3] + red[2][3] + red[3][3];
        float hb = -hbc[0] * hbc[0];
        float hy = -hyc[0] * hyc[0];
        float inv = 1.f / (1.f + rtc[0] * rtc[0] * rotor[b]);
        out[b * 5 + 0] = s0 * inv;
        out[b * 5 + 1] = s1 * hb * inv;
        out[b * 5 + 2] = s2 * hb * inv;
        out[b * 5 + 3] = s3 * hy * inv;
        out[b * 5 + 4] = duff[b] * vdc[0] * vdc[0] * inv;
    }
}

// ---------------- host side ----------------
extern "C" void kernel_launch(void* const* d_in, const int* in_sizes, int n_in,
                              void* d_out, int out_size) {
    (void)in_sizes; (void)n_in; (void)out_size;
    const float* h1      = (const float*)d_in[0];
    const float* adj1    = (const float*)d_in[1];
    const float* h2      = (const float*)d_in[2];
    const float* adj2    = (const float*)d_in[3];
    const float* A_int   = (const float*)d_in[4];
    const float* pos1    = (const float*)d_in[5];
    const float* pos2    = (const float*)d_in[6];
    const float* rotor   = (const float*)d_in[7];
    const float* vdw_r1  = (const float*)d_in[8];
    const float* vdw_r2  = (const float*)d_in[9];
    const float* duff    = (const float*)d_in[10];
    const float* nm1     = (const float*)d_in[11];
    const float* nm2     = (const float*)d_in[12];
    const float* node_W  = (const float*)d_in[13];
    const float* gat_W   = (const float*)d_in[14];
    const float* gat_b   = (const float*)d_in[15];
    const float* gat_A   = (const float*)d_in[16];
    const float* gate_W  = (const float*)d_in[17];
    const float* gate_b  = (const float*)d_in[18];
    const float* vdwA_W1 = (const float*)d_in[19];
    const float* vdwA_b1 = (const float*)d_in[20];
    const float* vdwA_W2 = (const float*)d_in[21];
    const float* vdwA_b2 = (const float*)d_in[22];
    const float* vdwB_W1 = (const float*)d_in[23];
    const float* vdwB_b1 = (const float*)d_in[24];
    const float* vdwB_W2 = (const float*)d_in[25];
    const float* vdwB_b2 = (const float*)d_in[26];
    const float* hbond   = (const float*)d_in[27];
    const float* hydro   = (const float*)d_in[28];
    const float* vdwc    = (const float*)d_in[29];
    const float* rotc    = (const float*)d_in[30];
    float* out = (float*)d_out;

    float *gp, *hp_, *hAp, *hpart, *e2p, *e1p, *wap, *bap;
    float *p1a, *p1b, *p2a, *p2b, *zap, *zbp, *partp;
    float2* statp;
    cudaGetSymbolAddress((void**)&gp,  g_g);
    cudaGetSymbolAddress((void**)&hp_, g_h);
    cudaGetSymbolAddress((void**)&hAp, g_hA);
    cudaGetSymbolAddress((void**)&hpart, g_hpart);
    cudaGetSymbolAddress((void**)&e2p, g_e2);
    cudaGetSymbolAddress((void**)&e1p, g_e1);
    cudaGetSymbolAddress((void**)&statp, g_stat);
    cudaGetSymbolAddress((void**)&wap, g_WA);
    cudaGetSymbolAddress((void**)&bap, g_bA);
    cudaGetSymbolAddress((void**)&p1a, g_P1A);
    cudaGetSymbolAddress((void**)&p1b, g_P1B);
    cudaGetSymbolAddress((void**)&p2a, g_P2A);
    cudaGetSymbolAddress((void**)&p2b, g_P2B);
    cudaGetSymbolAddress((void**)&zap, g_ZA);
    cudaGetSymbolAddress((void**)&zbp, g_ZB);
    cudaGetSymbolAddress((void**)&partp, g_part);

    // merged prologue + embedding
    k_pre<<<15, 256>>>(gat_W, gat_A, gat_b, wap, bap);
    k_embed_both<<<MROWS, DD>>>(h1, h2, node_W, gp);

    for (int l = 0; l < 3; l++) {
        const float* W  = gat_W  + (size_t)l * DD * DD;
        const float* bW = gat_b  + (size_t)l * DD;
        const float* WA = wap    + (size_t)l * DD * DD;
        const float* bA = bap    + (size_t)l * DD;
        const float* gW = gate_W + (size_t)l * 2 * DD;
        const float* gb = gate_b + l;
        k_dual<<<dim3(4, MROWS / 64, 1), 256>>>(gp, W, bW, WA, bA, hp_, hAp);
        k_ntsym<<<dim3(8, 8, 16), 256>>>(hp_, hAp, adj2, e2p, adj1, e1p);
        k_rowstat<<<BB * NN2 + BB * NN1, 128>>>(e2p, e1p, statp);
        k_hp<<<dim3(8, 8, 16), 256>>>(e2p, e1p, statp, hp_, hpart);
        k_gate<<<MROWS, DD>>>(gp, hpart, gW, gb);
    }

    // pair projections (one launch)
    k_proj<<<dim3(2, 64, 4), 256>>>(gp, vdwA_W1, vdwA_b1, vdwB_W1, vdwB_b1,
                                    p1a, p1b, p2a, p2b);
    // pair bilinear-relu MLP matrices
    k_zmat<<<dim3(16, 4, 16), 256>>>(p1a, p1b, p2a, p2b, vdwA_W2, vdwB_W2,
                                     vdwA_b2, vdwB_b2, zap, zbp);
    // physics + reductions
    k_phys<<<BB * NN1, 128>>>(zap, zbp, pos1, pos2, vdw_r1, vdw_r2, nm1, nm2,
                              A_int, partp);
    k_final<<<BB, 128>>>(partp, rotor, duff, hbond, hydro, vdwc, rotc, out);
}

// round 16
// speedup vs baseline: 1.1345x; 1.0621x over previous
#include <cuda_runtime.h>
#include <math.h>

#define BB  8
#define NN1 128
#define NN2 512
#define DD  128
#define MROWS (BB * (NN1 + NN2))   // 5120 combined rows
#define R1   (BB * NN1)            // 1024 graph-1 rows

// ---------------- static device scratch ----------------
__device__ float g_g  [MROWS * DD];
__device__ float g_h  [MROWS * DD];
__device__ float g_hA [MROWS * DD];
__device__ float g_hpart[4 * MROWS * DD];   // split-K partials for hp
__device__ float g_e2 [BB * NN2 * NN2];     // masked symmetric logits (graph2)
__device__ float g_e1 [BB * NN1 * NN1];
__device__ float2 g_stat[BB * NN2 + BB * NN1];  // per-row (max, 1/sum)
__device__ float g_WA [3 * DD * DD];
__device__ float g_bA [3 * DD];
__device__ float g_P1A[BB * NN1 * DD];
__device__ float g_P1B[BB * NN1 * DD];
__device__ float g_P2A[BB * NN2 * DD];
__device__ float g_P2B[BB * NN2 * DD];
__device__ float g_ZA [BB * NN1 * NN2];
__device__ float g_ZB [BB * NN1 * NN2];
__device__ float g_part[BB * NN1 * 4];

// ---------------- packed f32x2 helpers (Blackwell FFMA2) ----------------
__device__ __forceinline__ unsigned long long pk2(float x, float y) {
    unsigned long long r;
    asm("mov.b64 %0, {%1, %2};" : "=l"(r) : "f"(x), "f"(y));
    return r;
}
__device__ __forceinline__ unsigned long long dup2(float x) {
    unsigned long long r;
    asm("mov.b64 %0, {%1, %1};" : "=l"(r) : "f"(x));
    return r;
}
__device__ __forceinline__ void fma2(unsigned long long& acc, unsigned long long a,
                                     unsigned long long b) {
    asm("fma.rn.f32x2 %0, %1, %2, %0;" : "+l"(acc) : "l"(a), "l"(b));
}
__device__ __forceinline__ float2 unpk(unsigned long long v) {
    float2 r;
    asm("mov.b64 {%0, %1}, %2;" : "=f"(r.x), "=f"(r.y) : "l"(v));
    return r;
}

// ---------------- generic 64x64 NN GEMM body with register prefetch ----------------
__device__ __forceinline__ void gemm64k(const float* __restrict__ A, int lda,
                                        const float* __restrict__ B, int ldb,
                                        const float* __restrict__ bias,
                                        float* __restrict__ C, int ldc,
                                        int K, int m0, int n0) {
    __shared__ float As[16][68];
    __shared__ float Bs[16][68];
    int tid = threadIdx.x;
    int tx = tid & 15, ty = tid >> 4;
    int lm = tid >> 2, lkq = (tid & 3) * 4;
    int lk = tid >> 4, ln = (tid & 15) * 4;
    unsigned long long accp[4][2] = {};
    float4 a_pre = *(const float4*)&A[(long)(m0 + lm) * lda + lkq];
    float4 b_pre = *(const float4*)&B[(long)lk * ldb + n0 + ln];
    for (int k0 = 0; k0 < K; k0 += 16) {
        As[lkq + 0][lm] = a_pre.x; As[lkq + 1][lm] = a_pre.y;
        As[lkq + 2][lm] = a_pre.z; As[lkq + 3][lm] = a_pre.w;
        *(float4*)&Bs[lk][ln] = b_pre;
        __syncthreads();
        if (k0 + 16 < K) {
            a_pre = *(const float4*)&A[(long)(m0 + lm) * lda + k0 + 16 + lkq];
            b_pre = *(const float4*)&B[(long)(k0 + 16 + lk) * ldb + n0 + ln];
        }
        #pragma unroll
        for (int k = 0; k < 16; k++) {
            float4 av = *(float4*)&As[k][ty * 4];
            float4 bv = *(float4*)&Bs[k][tx * 4];
            unsigned long long b01 = pk2(bv.x, bv.y);
            unsigned long long b23 = pk2(bv.z, bv.w);
            float am[4] = {av.x, av.y, av.z, av.w};
            #pragma unroll
            for (int i = 0; i < 4; i++) {
                unsigned long long a2 = dup2(am[i]);
                fma2(accp[i][0], a2, b01);
                fma2(accp[i][1], a2, b23);
            }
        }
        __syncthreads();
    }
    #pragma unroll
    for (int i = 0; i < 4; i++) {
        int m = m0 + ty * 4 + i;
        int n = n0 + tx * 4;
        float2 c01 = unpk(accp[i][0]);
        float2 c23 = unpk(accp[i][1]);
        float4 v;
        v.x = c01.x + (bias ? bias[n + 0] : 0.f);
        v.y = c01.y + (bias ? bias[n + 1] : 0.f);
        v.z = c23.x + (bias ? bias[n + 2] : 0.f);
        v.w = c23.y + (bias ? bias[n + 3] : 0.f);
        *(float4*)&C[(long)m * ldc + n] = v;
    }
}

// merged prologue: blocks 0..11 WA[l]=W@A tiles; blocks 12..14 bA[l]=b@A
__global__ void k_pre(const float* __restrict__ W, const float* __restrict__ A,
                      const float* __restrict__ b, float* __restrict__ WA,
                      float* __restrict__ bA) {
    int bx = blockIdx.x;
    if (bx < 12) {
        int l = bx >> 2, t = bx & 3;
        gemm64k(W + (long)l * DD * DD, DD, A + (long)l * DD * DD, DD, nullptr,
                WA + (long)l * DD * DD, DD, DD, (t >> 1) * 64, (t & 1) * 64);
    } else {
        int l = bx - 12, n = threadIdx.x;
        if (n < DD) {
            float acc = 0.f;
            #pragma unroll 8
            for (int k = 0; k < DD; k++)
                acc += b[l * DD + k] * A[((long)l * DD + k) * DD + n];
            bA[l * DD + n] = acc;
        }
    }
}

// embedding for both graphs
__global__ void k_embed_both(const float* __restrict__ X1, const float* __restrict__ X2,
                             const float* __restrict__ W, float* __restrict__ Y) {
    int bn = blockIdx.x;
    const float* src = (bn < R1) ? X1 + (size_t)bn * 54
                                 : X2 + (size_t)(bn - R1) * 54;
    __shared__ float xs[54];
    if (threadIdx.x < 54) xs[threadIdx.x] = src[threadIdx.x];
    __syncthreads();
    int d = threadIdx.x;
    float acc = 0.f;
    #pragma unroll
    for (int l = 0; l < 54; l++) acc += xs[l] * W[l * DD + d];
    Y[(size_t)bn * DD + d] = acc;
}

// h = g@W + b ; hA = g@WA + bA  (one launch, 5120 rows)
__global__ void k_dual(const float* __restrict__ g, const float* __restrict__ W,
                       const float* __restrict__ b, const float* __restrict__ WA,
                       const float* __restrict__ bA, float* __restrict__ h,
                       float* __restrict__ hA) {
    int xi = blockIdx.x;
    const float* B; const float* bias; float* C; int n0;
    if (xi < 2) { B = W;  bias = b;  C = h;  n0 = xi * 64; }
    else        { B = WA; bias = bA; C = hA; n0 = (xi - 2) * 64; }
    gemm64k(g, DD, B, DD, bias, C, DD, DD, blockIdx.y * 64, n0);
}

// masked symmetric logits: L[m,n] = adj>0 ? (hA_m.h_n + h_m.hA_n) : -9e15
// 128x64 tile, 8x4 micro-tile (rows split ty*4 and 64+ty*4 to keep bank pattern)
__global__ void k_ntsym(const float* __restrict__ h, const float* __restrict__ hA,
                        const float* __restrict__ adj2, float* __restrict__ e2,
                        const float* __restrict__ adj1, float* __restrict__ e1) {
    int z = blockIdx.z;
    int N; const float* Hb; const float* Ab; const float* Adj; float* Cb;
    if (z < 8) {
        N = NN2;
        Hb = h  + ((long)R1 + (long)z * NN2) * DD;
        Ab = hA + ((long)R1 + (long)z * NN2) * DD;
        Adj = adj2 + (long)z * NN2 * NN2;
        Cb = e2 + (long)z * NN2 * NN2;
    } else {
        if (blockIdx.x >= 2 || blockIdx.y >= 1) return;
        N = NN1;
        Hb = h  + (long)(z - 8) * NN1 * DD;
        Ab = hA + (long)(z - 8) * NN1 * DD;
        Adj = adj1 + (long)(z - 8) * NN1 * NN1;
        Cb = e1 + (long)(z - 8) * NN1 * NN1;
    }
    __shared__ float AsA[16][132];
    __shared__ float AsH[16][132];
    __shared__ float BsH[16][68];
    __shared__ float BsA[16][68];
    int m0 = blockIdx.y * 128, n0 = blockIdx.x * 64;
    int tid = threadIdx.x;
    int tx = tid & 15, ty = tid >> 4;
    int ar = tid >> 1, ac = (tid & 1) * 8;   // A-side loader: row ar (0..127), 8 k's
    int lm = tid >> 2, lkq = (tid & 3) * 4;  // B-side loader: row lm (0..63), 4 k's
    unsigned long long accp[8][2] = {};
    long rowA = (long)(m0 + ar) * DD;
    long rowN = (long)(n0 + lm) * DD;
    float4 pA0 = *(const float4*)&Ab[rowA + ac];
    float4 pA1 = *(const float4*)&Ab[rowA + ac + 4];
    float4 pH0 = *(const float4*)&Hb[rowA + ac];
    float4 pH1 = *(const float4*)&Hb[rowA + ac + 4];
    float4 pbH = *(const float4*)&Hb[rowN + lkq];
    float4 pbA = *(const float4*)&Ab[rowN + lkq];
    for (int k0 = 0; k0 < DD; k0 += 16) {
        AsA[ac + 0][ar] = pA0.x; AsA[ac + 1][ar] = pA0.y;
        AsA[ac + 2][ar] = pA0.z; AsA[ac + 3][ar] = pA0.w;
        AsA[ac + 4][ar] = pA1.x; AsA[ac + 5][ar] = pA1.y;
        AsA[ac + 6][ar] = pA1.z; AsA[ac + 7][ar] = pA1.w;
        AsH[ac + 0][ar] = pH0.x; AsH[ac + 1][ar] = pH0.y;
        AsH[ac + 2][ar] = pH0.z; AsH[ac + 3][ar] = pH0.w;
        AsH[ac + 4][ar] = pH1.x; AsH[ac + 5][ar] = pH1.y;
        AsH[ac + 6][ar] = pH1.z; AsH[ac + 7][ar] = pH1.w;
        BsH[lkq + 0][lm] = pbH.x; BsH[lkq + 1][lm] = pbH.y;
        BsH[lkq + 2][lm] = pbH.z; BsH[lkq + 3][lm] = pbH.w;
        BsA[lkq + 0][lm] = pbA.x; BsA[lkq + 1][lm] = pbA.y;
        BsA[lkq + 2][lm] = pbA.z; BsA[lkq + 3][lm] = pbA.w;
        __syncthreads();
        if (k0 + 16 < DD) {
            pA0 = *(const float4*)&Ab[rowA + k0 + 16 + ac];
            pA1 = *(const float4*)&Ab[rowA + k0 + 16 + ac + 4];
            pH0 = *(const float4*)&Hb[rowA + k0 + 16 + ac];
            pH1 = *(const float4*)&Hb[rowA + k0 + 16 + ac + 4];
            pbH = *(const float4*)&Hb[rowN + k0 + 16 + lkq];
            pbA = *(const float4*)&Ab[rowN + k0 + 16 + lkq];
        }
        #pragma unroll
        for (int k = 0; k < 16; k++) {
            float4 aA0 = *(float4*)&AsA[k][ty * 4];
            float4 aA1 = *(float4*)&AsA[k][64 + ty * 4];
            float4 aH0 = *(float4*)&AsH[k][ty * 4];
            float4 aH1 = *(float4*)&AsH[k][64 + ty * 4];
            float4 bvH = *(float4*)&BsH[k][tx * 4];
            float4 bvA = *(float4*)&BsA[k][tx * 4];
            unsigned long long h01 = pk2(bvH.x, bvH.y);
            unsigned long long h23 = pk2(bvH.z, bvH.w);
            unsigned long long A01 = pk2(bvA.x, bvA.y);
            unsigned long long A23 = pk2(bvA.z, bvA.w);
            float amA[8] = {aA0.x, aA0.y, aA0.z, aA0.w, aA1.x, aA1.y, aA1.z, aA1.w};
            float amH[8] = {aH0.x, aH0.y, aH0.z, aH0.w, aH1.x, aH1.y, aH1.z, aH1.w};
            #pragma unroll
            for (int i = 0; i < 8; i++) {
                unsigned long long dA = dup2(amA[i]);
                unsigned long long dH = dup2(amH[i]);
                fma2(accp[i][0], dA, h01);
                fma2(accp[i][1], dA, h23);
                fma2(accp[i][0], dH, A01);
                fma2(accp[i][1], dH, A23);
            }
        }
        __syncthreads();
    }
    #pragma unroll
    for (int i = 0; i < 8; i++) {
        int mrow = (i < 4) ? (ty * 4 + i) : (64 + ty * 4 + i - 4);
        int m = m0 + mrow, n = n0 + tx * 4;
        float2 c01 = unpk(accp[i][0]);
        float2 c23 = unpk(accp[i][1]);
        float4 ad = *(const float4*)&Adj[(long)m * N + n];
        float4 v;
        v.x = (ad.x > 0.f) ? c01.x : -9e15f;
        v.y = (ad.y > 0.f) ? c01.y : -9e15f;
        v.z = (ad.z > 0.f) ? c23.x : -9e15f;
        v.w = (ad.w > 0.f) ? c23.y : -9e15f;
        *(float4*)&Cb[(long)m * N + n] = v;
    }
}

// per-row softmax stats: stat[row] = (max, 1/sum_exp). rows 0..4095: graph2; then graph1.
__global__ void k_rowstat(const float* __restrict__ e2, const float* __restrict__ e1,
                          float2* __restrict__ stat) {
    int bx = blockIdx.x;
    int t = threadIdx.x;
    int lane = t & 31, w = t >> 5;
    __shared__ float red[4];
    __shared__ float bcast;
    if (bx < BB * NN2) {
        const float* L = e2 + (long)bx * NN2;
        float v[4];
        float m = -3.4e38f;
        #pragma unroll
        for (int q = 0; q < 4; q++) { v[q] = L[t + 128 * q]; m = fmaxf(m, v[q]); }
        #pragma unroll
        for (int o = 16; o > 0; o >>= 1) m = fmaxf(m, __shfl_xor_sync(0xffffffffu, m, o));
        if (lane == 0) red[w] = m;
        __syncthreads();
        if (t == 0) bcast = fmaxf(fmaxf(red[0], red[1]), fmaxf(red[2], red[3]));
        __syncthreads();
        m = bcast;
        float s = 0.f;
        #pragma unroll
        for (int q = 0; q < 4; q++) s += __expf(v[q] - m);
        #pragma unroll
        for (int o = 16; o > 0; o >>= 1) s += __shfl_xor_sync(0xffffffffu, s, o);
        if (lane == 0) red[w] = s;
        __syncthreads();
        if (t == 0) {
            float ss = red[0] + red[1] + red[2] + red[3];
            stat[bx] = make_float2(m, 1.f / ss);
        }
    } else {
        int row = bx - BB * NN2;
        const float* L = e1 + (long)row * NN1;
        float v = L[t];
        float m = v;
        #pragma unroll
        for (int o = 16; o > 0; o >>= 1) m = fmaxf(m, __shfl_xor_sync(0xffffffffu, m, o));
        if (lane == 0) red[w] = m;
        __syncthreads();
        if (t == 0) bcast = fmaxf(fmaxf(red[0], red[1]), fmaxf(red[2], red[3]));
        __syncthreads();
        m = bcast;
        float s = __expf(v - m);
        #pragma unroll
        for (int o = 16; o > 0; o >>= 1) s += __shfl_xor_sync(0xffffffffu, s, o);
        if (lane == 0) red[w] = s;
        __syncthreads();
        if (t == 0) {
            float ss = red[0] + red[1] + red[2] + red[3];
            stat[bx] = make_float2(m, 1.f / ss);
        }
    }
}

// split-K hp GEMM (TN: hp = R^T @ h) with row-softmax applied on load + prefetch
__global__ void k_hp(const float* __restrict__ e2, const float* __restrict__ e1,
                     const float2* __restrict__ stat, const float* __restrict__ h,
                     float* __restrict__ part) {
    int z = blockIdx.z;
    const float* A; int lda, K, statbase;
    const float* B; float* C; int m0, n0;
    if (z < 8) {
        int chunk = blockIdx.x >> 1, nt = blockIdx.x & 1;
        A = e2 + (long)z * NN2 * NN2 + (long)chunk * 128 * NN2;
        lda = NN2; K = 128;
        statbase = z * NN2 + chunk * 128;
        B = h + ((long)R1 + (long)z * NN2 + chunk * 128) * DD;
        C = part + (long)chunk * MROWS * DD + ((long)R1 + (long)z * NN2) * DD;
        m0 = blockIdx.y * 64; n0 = nt * 64;
    } else {
        if (blockIdx.x >= 2 || blockIdx.y >= 2) return;
        A = e1 + (long)(z - 8) * NN1 * NN1;
        lda = NN1; K = NN1;
        statbase = BB * NN2 + (z - 8) * NN1;
        B = h + (long)(z - 8) * NN1 * DD;
        C = part + (long)(z - 8) * NN1 * DD;
        m0 = blockIdx.y * 64; n0 = blockIdx.x * 64;
    }
    __shared__ float As[16][68];
    __shared__ float Bs[16][68];
    int tid = threadIdx.x;
    int tx = tid & 15, ty = tid >> 4;
    int lk = tid >> 4, lq = (tid & 15) * 4;
    unsigned long long accp[4][2] = {};
    float2 st_pre = stat[statbase + lk];
    float4 a_pre = *(const float4*)&A[(long)lk * lda + m0 + lq];
    float4 b_pre = *(const float4*)&B[(long)lk * DD + n0 + lq];
    for (int k0 = 0; k0 < K; k0 += 16) {
        float4 a4;
        a4.x = __expf(a_pre.x - st_pre.x) * st_pre.y;
        a4.y = __expf(a_pre.y - st_pre.x) * st_pre.y;
        a4.z = __expf(a_pre.z - st_pre.x) * st_pre.y;
        a4.w = __expf(a_pre.w - st_pre.x) * st_pre.y;
        *(float4*)&As[lk][lq] = a4;
        *(float4*)&Bs[lk][lq] = b_pre;
        __syncthreads();
        if (k0 + 16 < K) {
            st_pre = stat[statbase + k0 + 16 + lk];
            a_pre = *(const float4*)&A[(long)(k0 + 16 + lk) * lda + m0 + lq];
            b_pre = *(const float4*)&B[(long)(k0 + 16 + lk) * DD + n0 + lq];
        }
        #pragma unroll
        for (int k = 0; k < 16; k++) {
            float4 av = *(float4*)&As[k][ty * 4];
            float4 bv = *(float4*)&Bs[k][tx * 4];
            unsigned long long b01 = pk2(bv.x, bv.y);
            unsigned long long b23 = pk2(bv.z, bv.w);
            float am[4] = {av.x, av.y, av.z, av.w};
            #pragma unroll
            for (int i = 0; i < 4; i++) {
                unsigned long long a2 = dup2(am[i]);
                fma2(accp[i][0], a2, b01);
                fma2(accp[i][1], a2, b23);
            }
        }
        __syncthreads();
    }
    #pragma unroll
    for (int i = 0; i < 4; i++) {
        int m = m0 + ty * 4 + i, n = n0 + tx * 4;
        float2 c01 = unpk(accp[i][0]);
        float2 c23 = unpk(accp[i][1]);
        float4 v = {c01.x, c01.y, c23.x, c23.y};
        *(float4*)&C[(long)m * DD + n] = v;
    }
}

// gate: hp = relu(sum chunks); c = sigmoid(g.gW1 + hp.gW2 + gb); g = c*g + (1-c)*hp
__global__ void k_gate(float* __restrict__ g, const float* __restrict__ part,
                       const float* __restrict__ gW, const float* __restrict__ gb) {
    long row = blockIdx.x;
    int t = threadIdx.x;
    float hp = part[row * DD + t];
    if (row >= R1) {
        hp += part[(long)1 * MROWS * DD + row * DD + t];
        hp += part[(long)2 * MROWS * DD + row * DD + t];
        hp += part[(long)3 * MROWS * DD + row * DD + t];
    }
    hp = fmaxf(hp, 0.f);
    float x = g[row * DD + t];
    float v = x * gW[t] + hp * gW[DD + t];
    #pragma unroll
    for (int o = 16; o > 0; o >>= 1) v += __shfl_down_sync(0xffffffffu, v, o);
    __shared__ float red[4];
    __shared__ float csh;
    if ((t & 31) == 0) red[t >> 5] = v;
    __syncthreads();
    if (t == 0) {
        float s = red[0] + red[1] + red[2] + red[3] + gb[0];
        csh = 1.f / (1.f + __expf(-s));
    }
    __syncthreads();
    float c = csh;
    g[row * DD + t] = c * x + (1.f - c) * hp;
}

// all 4 pair projections in one launch (z: 0=p1a 1=p1b 2=p2a 3=p2b)
__global__ void k_proj(const float* __restrict__ g,
                       const float* __restrict__ WA1, const float* __restrict__ bA1,
                       const float* __restrict__ WB1, const float* __restrict__ bB1,
                       float* __restrict__ p1a, float* __restrict__ p1b,
                       float* __restrict__ p2a, float* __restrict__ p2b) {
    int z = blockIdx.z;
    const float* A; const float* B; const float* bias; float* C; int mt;
    switch (z) {
        case 0: A = g;            B = WA1;           bias = bA1;   C = p1a; mt = R1 / 64; break;
        case 1: A = g;            B = WB1;           bias = bB1;   C = p1b; mt = R1 / 64; break;
        case 2: A = g + (long)R1 * DD; B = WA1 + DD * DD; bias = nullptr; C = p2a; mt = (BB * NN2) / 64; break;
        default:A = g + (long)R1 * DD; B = WB1 + DD * DD; bias = nullptr; C = p2b; mt = (BB * NN2) / 64; break;
    }
    if ((int)blockIdx.y >= mt) return;
    gemm64k(A, DD, B, DD, bias, C, DD, DD, blockIdx.y * 64, blockIdx.x * 64);
}

// Z[b,i,j] = act( b2 + sum_h relu(P1[i,h]+P2[j,h]) * w2[h] ), 32x32 tiles
__global__ void k_zmat(const float* __restrict__ p1a, const float* __restrict__ p1b,
                       const float* __restrict__ p2a, const float* __restrict__ p2b,
                       const float* __restrict__ w2A, const float* __restrict__ w2B,
                       const float* __restrict__ b2A, const float* __restrict__ b2B,
                       float* __restrict__ ZA, float* __restrict__ ZB) {
    __shared__ float P1s[DD][33];
    __shared__ float P2s[DD][33];
    __shared__ float w2s[DD];
    int z = blockIdx.z;
    int b = z >> 1, mlp = z & 1;
    const float* P1 = (mlp ? p1b : p1a) + (long)b * NN1 * DD;
    const float* P2 = (mlp ? p2b : p2a) + (long)b * NN2 * DD;
    const float* w2 = mlp ? w2B : w2A;
    float b2 = mlp ? b2B[0] : b2A[0];
    float* Z = (mlp ? ZB : ZA) + (long)b * NN1 * NN2;
    int i0 = blockIdx.y * 32, j0 = blockIdx.x * 32;
    int tid = threadIdx.x;
    if (tid < DD) w2s[tid] = w2[tid];
    {
        int row = tid >> 3, cb = (tid & 7) * 16;
        #pragma unroll
        for (int q = 0; q < 4; q++) {
            float4 v1 = *(const float4*)&P1[(long)(i0 + row) * DD + cb + q * 4];
            float4 v2 = *(const float4*)&P2[(long)(j0 + row) * DD + cb + q * 4];
            P1s[cb + q * 4 + 0][row] = v1.x; P1s[cb + q * 4 + 1][row] = v1.y;
            P1s[cb + q * 4 + 2][row] = v1.z; P1s[cb + q * 4 + 3][row] = v1.w;
            P2s[cb + q * 4 + 0][row] = v2.x; P2s[cb + q * 4 + 1][row] = v2.y;
            P2s[cb + q * 4 + 2][row] = v2.z; P2s[cb + q * 4 + 3][row] = v2.w;
        }
    }
    __syncthreads();
    int tx = tid & 15, ty = tid >> 4;
    float a00 = 0.f, a01 = 0.f, a10 = 0.f, a11 = 0.f;
    #pragma unroll 4
    for (int k = 0; k < DD; k++) {
        float w = w2s[k];
        float p0 = P1s[k][ty], p1 = P1s[k][ty + 16];
        float q0 = P2s[k][tx], q1 = P2s[k][tx + 16];
        a00 += fmaxf(p0 + q0, 0.f) * w;
        a01 += fmaxf(p0 + q1, 0.f) * w;
        a10 += fmaxf(p1 + q0, 0.f) * w;
        a11 += fmaxf(p1 + q1, 0.f) * w;
    }
    a00 += b2; a01 += b2; a10 += b2; a11 += b2;
    if (mlp == 0) {
        a00 = 1.f / (1.f + __expf(-a00)); a01 = 1.f / (1.f + __expf(-a01));
        a10 = 1.f / (1.f + __expf(-a10)); a11 = 1.f / (1.f + __expf(-a11));
    } else {
        a00 = tanhf(a00) * 0.2f; a01 = tanhf(a01) * 0.2f;
        a10 = tanhf(a10) * 0.2f; a11 = tanhf(a11) * 0.2f;
    }
    Z[(long)(i0 + ty) * NN2 + j0 + tx]           = a00;
    Z[(long)(i0 + ty) * NN2 + j0 + tx + 16]      = a01;
    Z[(long)(i0 + ty + 16) * NN2 + j0 + tx]      = a10;
    Z[(long)(i0 + ty + 16) * NN2 + j0 + tx + 16] = a11;
}

// elementwise physics + per-(b,i) reduction
__global__ void k_phys(const float* __restrict__ ZA, const float* __restrict__ ZB,
                       const float* __restrict__ pos1, const float* __restrict__ pos2,
                       const float* __restrict__ r1, const float* __restrict__ r2,
                       const float* __restrict__ nm1, const float* __restrict__ nm2,
                       const float* __restrict__ A_int, float* __restrict__ part) {
    int b = blockIdx.x >> 7, i = blockIdx.x & 127;
    int t = threadIdx.x;
    float px = pos1[(b * NN1 + i) * 3 + 0];
    float py = pos1[(b * NN1 + i) * 3 + 1];
    float pz = pos1[(b * NN1 + i) * 3 + 2];
    float rr1 = r1[b * NN1 + i];
    float m1  = nm1[b * NN1 + i];
    size_t zbase = (size_t)b * NN1 * NN2 + (size_t)i * NN2;
    size_t abase = (size_t)b * 8 * NN1 * NN2 + (size_t)i * NN2;
    const size_t chw = (size_t)NN1 * NN2;
    float s0 = 0.f, s1 = 0.f, s2 = 0.f, s3 = 0.f;
    for (int j = t; j < NN2; j += 128) {
        float Aw = ZA[zbase + j];
        float Bw = ZB[zbase + j];
        float dx = px - pos2[(b * NN2 + j) * 3 + 0];
        float dy = py - pos2[(b * NN2 + j) * 3 + 1];
        float dz = pz - pos2[(b * NN2 + j) * 3 + 2];
        float dm = sqrtf(dx * dx + dy * dy + dz * dz + 1e-10f);
        if (dm < 0.5f) dm = 1e10f;
        float dm0 = rr1 + r2[b * NN2 + j] + Bw;
        float dm0s = (dm0 < 1e-4f) ? 1.f : dm0;
        float rq = dm0s / dm;
        float rq2 = rq * rq;
        float r6 = rq2 * rq2 * rq2;
        float evdw = fminf(r6 * r6 - 2.f * r6, 100.f);
        float Aamp = Aw * (0.0356f - 0.0178f) + 0.0178f;
        s0 += Aamp * evdw * m1 * nm2[b * NN2 + j];
        float dmd = dm - dm0;
        float a1 = A_int[abase + 1 * chw + j];
        float a7 = A_int[abase + 7 * chw + j];
        float a6 = A_int[abase + 6 * chw + j];
        s1 += fminf(fmaxf(dmd * a1 * (-1.f / 0.7f), 0.f), 1.f);
        s2 += fminf(fmaxf(dmd * a7 * (-1.f / 0.7f), 0.f), 1.f);
        s3 += fminf(fmaxf((1.5f - dmd) * a6, 0.f), 1.f);
    }
    #pragma unroll
    for (int o = 16; o > 0; o >>= 1) {
        s0 += __shfl_down_sync(0xffffffffu, s0, o);
        s1 += __shfl_down_sync(0xffffffffu, s1, o);
        s2 += __shfl_down_sync(0xffffffffu, s2, o);
        s3 += __shfl_down_sync(0xffffffffu, s3, o);
    }
    __shared__ float acc[4][4];
    int lane = t & 31, w = t >> 5;
    if (lane == 0) { acc[w][0] = s0; acc[w][1] = s1; acc[w][2] = s2; acc[w][3] = s3; }
    __syncthreads();
    if (t < 4)
        part[((size_t)b * NN1 + i) * 4 + t] = acc[0][t] + acc[1][t] + acc[2][t] + acc[3][t];
}

__global__ void k_final(const float* __restrict__ part, const float* __restrict__ rotor,
                        const float* __restrict__ duff, const float* __restrict__ hbc,
                        const float* __restrict__ hyc, const float* __restrict__ vdc,
                        const float* __restrict__ rtc, float* __restrict__ out) {
    int b = blockIdx.x, t = threadIdx.x;
    size_t base = ((size_t)b * NN1 + t) * 4;
    float v0 = part[base + 0], v1 = part[base + 1], v2 = part[base + 2], v3 = part[base + 3];
    #pragma unroll
    for (int o = 16; o > 0; o >>= 1) {
        v0 += __shfl_down_sync(0xffffffffu, v0, o);
        v1 += __shfl_down_sync(0xffffffffu, v1, o);
        v2 += __shfl_down_sync(0xffffffffu, v2, o);
        v3 += __shfl_down_sync(0xffffffffu, v3, o);
    }
    __shared__ float red[4][4];
    if ((t & 31) == 0) {
        int w = t >> 5;
        red[w][0] = v0; red[w][1] = v1; red[w][2] = v2; red[w][3] = v3;
    }
    __syncthreads();
    if (t == 0) {
        float s0 = red[0][0] + red[1][0] + red[2][0] + red[3][0];
        float s1 = red[0][1] + red[1][1] + red[2][1] + red[3][1];
        float s2 = red[0][2] + red[1][2] + red[2][2] + red[3][2];
        float s3 = red[0][3] + red[1][3] + red[2][3] + red[3][3];
        float hb = -hbc[0] * hbc[0];
        float hy = -hyc[0] * hyc[0];
        float inv = 1.f / (1.f + rtc[0] * rtc[0] * rotor[b]);
        out[b * 5 + 0] = s0 * inv;
        out[b * 5 + 1] = s1 * hb * inv;
        out[b * 5 + 2] = s2 * hb * inv;
        out[b * 5 + 3] = s3 * hy * inv;
        out[b * 5 + 4] = duff[b] * vdc[0] * vdc[0] * inv;
    }
}

// ---------------- host side ----------------
extern "C" void kernel_launch(void* const* d_in, const int* in_sizes, int n_in,
                              void* d_out, int out_size) {
    (void)in_sizes; (void)n_in; (void)out_size;
    const float* h1      = (const float*)d_in[0];
    const float* adj1    = (const float*)d_in[1];
    const float* h2      = (const float*)d_in[2];
    const float* adj2    = (const float*)d_in[3];
    const float* A_int   = (const float*)d_in[4];
    const float* pos1    = (const float*)d_in[5];
    const float* pos2    = (const float*)d_in[6];
    const float* rotor   = (const float*)d_in[7];
    const float* vdw_r1  = (const float*)d_in[8];
    const float* vdw_r2  = (const float*)d_in[9];
    const float* duff    = (const float*)d_in[10];
    const float* nm1     = (const float*)d_in[11];
    const float* nm2     = (const float*)d_in[12];
    const float* node_W  = (const float*)d_in[13];
    const float* gat_W   = (const float*)d_in[14];
    const float* gat_b   = (const float*)d_in[15];
    const float* gat_A   = (const float*)d_in[16];
    const float* gate_W  = (const float*)d_in[17];
    const float* gate_b  = (const float*)d_in[18];
    const float* vdwA_W1 = (const float*)d_in[19];
    const float* vdwA_b1 = (const float*)d_in[20];
    const float* vdwA_W2 = (const float*)d_in[21];
    const float* vdwA_b2 = (const float*)d_in[22];
    const float* vdwB_W1 = (const float*)d_in[23];
    const float* vdwB_b1 = (const float*)d_in[24];
    const float* vdwB_W2 = (const float*)d_in[25];
    const float* vdwB_b2 = (const float*)d_in[26];
    const float* hbond   = (const float*)d_in[27];
    const float* hydro   = (const float*)d_in[28];
    const float* vdwc    = (const float*)d_in[29];
    const float* rotc    = (const float*)d_in[30];
    float* out = (float*)d_out;

    float *gp, *hp_, *hAp, *hpart, *e2p, *e1p, *wap, *bap;
    float *p1a, *p1b, *p2a, *p2b, *zap, *zbp, *partp;
    float2* statp;
    cudaGetSymbolAddress((void**)&gp,  g_g);
    cudaGetSymbolAddress((void**)&hp_, g_h);
    cudaGetSymbolAddress((void**)&hAp, g_hA);
    cudaGetSymbolAddress((void**)&hpart, g_hpart);
    cudaGetSymbolAddress((void**)&e2p, g_e2);
    cudaGetSymbolAddress((void**)&e1p, g_e1);
    cudaGetSymbolAddress((void**)&statp, g_stat);
    cudaGetSymbolAddress((void**)&wap, g_WA);
    cudaGetSymbolAddress((void**)&bap, g_bA);
    cudaGetSymbolAddress((void**)&p1a, g_P1A);
    cudaGetSymbolAddress((void**)&p1b, g_P1B);
    cudaGetSymbolAddress((void**)&p2a, g_P2A);
    cudaGetSymbolAddress((void**)&p2b, g_P2B);
    cudaGetSymbolAddress((void**)&zap, g_ZA);
    cudaGetSymbolAddress((void**)&zbp, g_ZB);
    cudaGetSymbolAddress((void**)&partp, g_part);

    // merged prologue + embedding
    k_pre<<<15, 256>>>(gat_W, gat_A, gat_b, wap, bap);
    k_embed_both<<<MROWS, DD>>>(h1, h2, node_W, gp);

    for (int l = 0; l < 3; l++) {
        const float* W  = gat_W  + (size_t)l * DD * DD;
        const float* bW = gat_b  + (size_t)l * DD;
        const float* WA = wap    + (size_t)l * DD * DD;
        const float* bA = bap    + (size_t)l * DD;
        const float* gW = gate_W + (size_t)l * 2 * DD;
        const float* gb = gate_b + l;
        k_dual<<<dim3(4, MROWS / 64, 1), 256>>>(gp, W, bW, WA, bA, hp_, hAp);
        k_ntsym<<<dim3(8, 4, 16), 256>>>(hp_, hAp, adj2, e2p, adj1, e1p);
        k_rowstat<<<BB * NN2 + BB * NN1, 128>>>(e2p, e1p, statp);
        k_hp<<<dim3(8, 8, 16), 256>>>(e2p, e1p, statp, hp_, hpart);
        k_gate<<<MROWS, DD>>>(gp, hpart, gW, gb);
    }

    // pair projections (one launch)
    k_proj<<<dim3(2, 64, 4), 256>>>(gp, vdwA_W1, vdwA_b1, vdwB_W1, vdwB_b1,
                                    p1a, p1b, p2a, p2b);
    // pair bilinear-relu MLP matrices
    k_zmat<<<dim3(16, 4, 16), 256>>>(p1a, p1b, p2a, p2b, vdwA_W2, vdwB_W2,
                                     vdwA_b2, vdwB_b2, zap, zbp);
    // physics + reductions
    k_phys<<<BB * NN1, 128>>>(zap, zbp, pos1, pos2, vdw_r1, vdw_r2, nm1, nm2,
                              A_int, partp);
    k_final<<<BB, 128>>>(partp, rotor, duff, hbond, hydro, vdwc, rotc, out);
}